// round 6
// baseline (speedup 1.0000x reference)
#include <cuda_runtime.h>
#include <cstdint>
#include <cstddef>

#define BB 2
#define SS 2048
#define DD 768
#define HH 12
#define DK 64
#define DFF 3072
#define MM (BB*SS)                 // 4096
#define X2_ELEMS ((size_t)MM*DD)   // 3145728

// ---------------- scratch (static device globals; no allocation) -------------
__device__ float g_Q[(size_t)MM*DD];
__device__ float g_K[(size_t)MM*DD];
__device__ float g_V[(size_t)MM*DD];
__device__ float g_ctx[(size_t)MM*DD];
__device__ float g_x1[(size_t)MM*DD];
__device__ float g_t2[(size_t)MM*DD];
__device__ float g_ff[(size_t)MM*DFF];
// rounded copies of GEMM inputs
__device__ float g_xr[(size_t)MM*DD];
__device__ float g_Wqr[(size_t)DD*DD];
__device__ float g_Wkr[(size_t)DD*DD];
__device__ float g_Wvr[(size_t)DD*DD];
__device__ float g_Wor[(size_t)DD*DD];
__device__ float g_W1r[(size_t)DD*DFF];
__device__ float g_W2r[(size_t)DFF*DD];

// ---------------- helpers ----------------------------------------------------
__device__ __forceinline__ float rtf(float v) {       // round-to-nearest tf32
    uint32_t r;
    asm("cvt.rna.tf32.f32 %0, %1;" : "=r"(r) : "f"(v));
    return __uint_as_float(r);
}

__device__ __forceinline__ void mma8(float* c, const uint32_t* a, const uint32_t* b) {
    asm volatile(
        "mma.sync.aligned.m16n8k8.row.col.f32.tf32.tf32.f32 "
        "{%0,%1,%2,%3},{%4,%5,%6,%7},{%8,%9},{%0,%1,%2,%3};\n"
        : "+f"(c[0]), "+f"(c[1]), "+f"(c[2]), "+f"(c[3])
        : "r"(a[0]), "r"(a[1]), "r"(a[2]), "r"(a[3]), "r"(b[0]), "r"(b[1]));
}

__device__ __forceinline__ void cp16(uint32_t smem_addr, const void* gptr) {
    asm volatile("cp.async.cg.shared.global [%0], [%1], 16;\n"
                 :: "r"(smem_addr), "l"(gptr));
}
__device__ __forceinline__ void cp_commit() {
    asm volatile("cp.async.commit_group;\n" ::: "memory");
}
template<int N>
__device__ __forceinline__ void cp_wait() {
    asm volatile("cp.async.wait_group %0;\n" :: "n"(N) : "memory");
}

// ---------------- merged elementwise tf32 pre-round (7 segments) --------------
__global__ void round_all(
    const float4* __restrict__ x,  float4* __restrict__ xr,
    const float4* __restrict__ wq, float4* __restrict__ wqr,
    const float4* __restrict__ wk, float4* __restrict__ wkr,
    const float4* __restrict__ wv, float4* __restrict__ wvr,
    const float4* __restrict__ wo, float4* __restrict__ wor,
    const float4* __restrict__ w1, float4* __restrict__ w1r,
    const float4* __restrict__ w2, float4* __restrict__ w2r)
{
    constexpr int SX = MM*DD/4, SW = DD*DD/4, SF = DD*DFF/4;
    int i = blockIdx.x * blockDim.x + threadIdx.x;
    const float4* in; float4* out; int off;
    if      (i < SX)                  { in = x;  out = xr;  off = 0; }
    else if (i < SX + SW)             { in = wq; out = wqr; off = SX; }
    else if (i < SX + 2*SW)           { in = wk; out = wkr; off = SX + SW; }
    else if (i < SX + 3*SW)           { in = wv; out = wvr; off = SX + 2*SW; }
    else if (i < SX + 4*SW)           { in = wo; out = wor; off = SX + 3*SW; }
    else if (i < SX + 4*SW + SF)      { in = w1; out = w1r; off = SX + 4*SW; }
    else if (i < SX + 4*SW + 2*SF)    { in = w2; out = w2r; off = SX + 4*SW + SF; }
    else return;
    int j = i - off;
    float4 v = in[j];
    v.x = rtf(v.x); v.y = rtf(v.y); v.z = rtf(v.z); v.w = rtf(v.w);
    out[j] = v;
}

// ---------------- generic TF32 tensor-core GEMM (cp.async double buffer) -----
template<int BM, int BN, int WM, int WN, bool TB, bool QKV>
__global__ void __launch_bounds__(256, 2) gemm_tf32(
    const float* __restrict__ A,
    const float* __restrict__ B0, const float* __restrict__ bias0, float* __restrict__ C0,
    const float* __restrict__ B1p, const float* __restrict__ bias1p, float* __restrict__ C1p,
    const float* __restrict__ B2p, const float* __restrict__ bias2p, float* __restrict__ C2p,
    int K, int lda, int ldb, int ldc,
    long long sA1, long long sA2, long long sB1, long long sB2,
    long long sC1, long long sC2, float alpha, int relu, int rnd)
{
    constexpr int MI  = WM / 16;
    constexpr int NJ  = WN / 8;
    constexpr int WGN = BN / WN;
    constexpr int ASTR = 40;
    constexpr int BSTR = TB ? 40 : (BN + 4);
    constexpr int ASZ  = BM * ASTR;
    constexpr int BSZ  = TB ? (BN * 40) : (32 * (BN + 4));
    constexpr int NAV  = BM * 8 / 256;
    constexpr int NBV  = TB ? (BN * 8 / 256) : (8 * BN / 256);

    __shared__ float As[2 * ASZ];
    __shared__ float Bs[2 * BSZ];

    const int tid  = threadIdx.x;
    const int wid  = tid >> 5;
    const int lane = tid & 31;
    const int g    = lane >> 2;
    const int tg   = lane & 3;
    const int wm   = (wid / WGN) * WM;
    const int wn   = (wid % WGN) * WN;

    const float* B    = B0;
    const float* bias = bias0;
    float*       C    = C0;
    long long zb = 0, zh = 0;
    if (QKV) {
        int z = blockIdx.z;
        if (z == 1) { B = B1p; bias = bias1p; C = C1p; }
        else if (z == 2) { B = B2p; bias = bias2p; C = C2p; }
    } else {
        int z = blockIdx.z;
        zb = z / HH; zh = z % HH;
    }

    const float* Ab = A + zb * sA1 + zh * sA2 + (size_t)blockIdx.y * BM * lda;
    const float* Bb = B + zb * sB1 + zh * sB2 +
                      (TB ? (size_t)blockIdx.x * BN * ldb : (size_t)blockIdx.x * BN);
    float* Cb = C + zb * sC1 + zh * sC2 +
                (size_t)blockIdx.y * BM * ldc + (size_t)blockIdx.x * BN;

    const uint32_t sA_base = (uint32_t)__cvta_generic_to_shared(As);
    const uint32_t sB_base = (uint32_t)__cvta_generic_to_shared(Bs);

    auto issue = [&](int k0, int st) {
        uint32_t abuf = sA_base + st * ASZ * 4;
#pragma unroll
        for (int i = 0; i < NAV; i++) {
            int idx = tid + i * 256;
            int m = idx >> 3, cv = idx & 7;
            cp16(abuf + (m * ASTR + cv * 4) * 4,
                 Ab + (size_t)m * lda + k0 + cv * 4);
        }
        uint32_t bbuf = sB_base + st * BSZ * 4;
#pragma unroll
        for (int i = 0; i < NBV; i++) {
            int idx = tid + i * 256;
            if (TB) {
                int n = idx >> 3, cv = idx & 7;
                cp16(bbuf + (n * BSTR + cv * 4) * 4,
                     Bb + (size_t)n * ldb + k0 + cv * 4);
            } else {
                int r = idx / (BN / 4), cv = idx % (BN / 4);
                cp16(bbuf + (r * BSTR + cv * 4) * 4,
                     Bb + (size_t)(k0 + r) * ldb + cv * 4);
            }
        }
        cp_commit();
    };

    float c[MI][NJ][4];
#pragma unroll
    for (int mi = 0; mi < MI; mi++)
#pragma unroll
        for (int j = 0; j < NJ; j++)
#pragma unroll
            for (int r = 0; r < 4; r++) c[mi][j][r] = 0.f;

    const int nK = K / 32;
    issue(0, 0);

    for (int kc = 0; kc < nK; kc++) {
        const int st = kc & 1;
        if (kc + 1 < nK) {
            issue((kc + 1) * 32, st ^ 1);
            cp_wait<1>();
        } else {
            cp_wait<0>();
        }
        __syncthreads();

        const float* Ac = As + st * ASZ;
        const float* Bc = Bs + st * BSZ;
#pragma unroll
        for (int kk = 0; kk < 4; kk++) {
            const int ks = kk * 8;
            uint32_t af[MI][4], bf[NJ][2];
#pragma unroll
            for (int mi = 0; mi < MI; mi++) {
                int m = wm + mi * 16 + g;
                float2 p0 = *(const float2*)&Ac[m * ASTR + ks + 2 * tg];
                float2 p1 = *(const float2*)&Ac[(m + 8) * ASTR + ks + 2 * tg];
                af[mi][0] = __float_as_uint(p0.x);
                af[mi][1] = __float_as_uint(p1.x);
                af[mi][2] = __float_as_uint(p0.y);
                af[mi][3] = __float_as_uint(p1.y);
            }
#pragma unroll
            for (int j = 0; j < NJ; j++) {
                int n = wn + j * 8 + g;
                if (TB) {
                    float2 q = *(const float2*)&Bc[n * BSTR + ks + 2 * tg];
                    bf[j][0] = __float_as_uint(q.x);
                    bf[j][1] = __float_as_uint(q.y);
                } else {
                    bf[j][0] = __float_as_uint(Bc[(ks + 2 * tg)     * BSTR + n]);
                    bf[j][1] = __float_as_uint(Bc[(ks + 2 * tg + 1) * BSTR + n]);
                }
            }
#pragma unroll
            for (int mi = 0; mi < MI; mi++)
#pragma unroll
                for (int j = 0; j < NJ; j++) mma8(c[mi][j], af[mi], bf[j]);
        }
        __syncthreads();
    }

#pragma unroll
    for (int mi = 0; mi < MI; mi++) {
        int r0 = wm + mi * 16 + g;
#pragma unroll
        for (int j = 0; j < NJ; j++) {
            int col = wn + j * 8 + tg * 2;
            float2 bb = make_float2(0.f, 0.f);
            if (bias) bb = *(const float2*)(bias + (size_t)blockIdx.x * BN + col);
            float v0 = c[mi][j][0] * alpha + bb.x;
            float v1 = c[mi][j][1] * alpha + bb.y;
            float v2 = c[mi][j][2] * alpha + bb.x;
            float v3 = c[mi][j][3] * alpha + bb.y;
            if (relu) {
                v0 = fmaxf(v0, 0.f); v1 = fmaxf(v1, 0.f);
                v2 = fmaxf(v2, 0.f); v3 = fmaxf(v3, 0.f);
            }
            if (rnd) { v0 = rtf(v0); v1 = rtf(v1); v2 = rtf(v2); v3 = rtf(v3); }
            *(float2*)(Cb + (size_t)r0 * ldc + col)       = make_float2(v0, v1);
            *(float2*)(Cb + (size_t)(r0 + 8) * ldc + col) = make_float2(v2, v3);
        }
    }
}

// ---------------- scores: single-shot K=64, 128x128 tile ---------------------
__global__ void __launch_bounds__(256, 2) scores_k64(
    const float* __restrict__ Q, const float* __restrict__ Km, float* __restrict__ attn)
{
    constexpr int STR = 72;
    __shared__ float As[128 * STR];
    __shared__ float Bs[128 * STR];

    const int tid  = threadIdx.x;
    const int wid  = tid >> 5;
    const int lane = tid & 31;
    const int g    = lane >> 2;
    const int tg   = lane & 3;
    const int wm   = (wid >> 2) * 64;
    const int wn   = (wid & 3) * 32;

    const int z = blockIdx.z;
    const int b = z / HH, h = z % HH;
    const size_t base = (size_t)b * SS * DD + (size_t)h * DK;
    const int row0 = blockIdx.y * 128;
    const int col0 = blockIdx.x * 128;

    const uint32_t sA = (uint32_t)__cvta_generic_to_shared(As);
    const uint32_t sB = (uint32_t)__cvta_generic_to_shared(Bs);

#pragma unroll
    for (int i = 0; i < 8; i++) {
        int idx = tid + i * 256;
        int m = idx >> 4, cv = idx & 15;
        cp16(sA + (m * STR + cv * 4) * 4, Q  + base + (size_t)(row0 + m) * DD + cv * 4);
        cp16(sB + (m * STR + cv * 4) * 4, Km + base + (size_t)(col0 + m) * DD + cv * 4);
    }
    cp_commit();
    cp_wait<0>();
    __syncthreads();

    float c[4][4][4];
#pragma unroll
    for (int mi = 0; mi < 4; mi++)
#pragma unroll
        for (int j = 0; j < 4; j++)
#pragma unroll
            for (int r = 0; r < 4; r++) c[mi][j][r] = 0.f;

#pragma unroll
    for (int kk = 0; kk < 8; kk++) {
        const int ks = kk * 8;
        uint32_t af[4][4], bf[4][2];
#pragma unroll
        for (int mi = 0; mi < 4; mi++) {
            int m = wm + mi * 16 + g;
            float2 p0 = *(const float2*)&As[m * STR + ks + 2 * tg];
            float2 p1 = *(const float2*)&As[(m + 8) * STR + ks + 2 * tg];
            af[mi][0] = __float_as_uint(p0.x);
            af[mi][1] = __float_as_uint(p1.x);
            af[mi][2] = __float_as_uint(p0.y);
            af[mi][3] = __float_as_uint(p1.y);
        }
#pragma unroll
        for (int j = 0; j < 4; j++) {
            int n = wn + j * 8 + g;
            float2 q = *(const float2*)&Bs[n * STR + ks + 2 * tg];
            bf[j][0] = __float_as_uint(q.x);
            bf[j][1] = __float_as_uint(q.y);
        }
#pragma unroll
        for (int mi = 0; mi < 4; mi++)
#pragma unroll
            for (int j = 0; j < 4; j++) mma8(c[mi][j], af[mi], bf[j]);
    }

    float* out = attn + (size_t)z * SS * SS;
#pragma unroll
    for (int mi = 0; mi < 4; mi++) {
        int r0 = row0 + wm + mi * 16 + g;
#pragma unroll
        for (int j = 0; j < 4; j++) {
            int col = col0 + wn + j * 8 + tg * 2;
            *(float2*)(out + (size_t)r0 * SS + col) =
                make_float2(c[mi][j][0] * 0.125f, c[mi][j][1] * 0.125f);
            *(float2*)(out + (size_t)(r0 + 8) * SS + col) =
                make_float2(c[mi][j][2] * 0.125f, c[mi][j][3] * 0.125f);
        }
    }
}

// ---------------- fused softmax + ctx -----------------------------------------
// One block owns 128 q-rows of one (b,h). Pass1: per-row max & sum (scores read
// twice, 2nd L2-hot). Pass2: normalize+round, write attn once, MMA with V into
// ctx accumulators. attn gmem value == value used in P @ V.
#define PSTR 72
#define VSTR 68
#define CHUNK 64
__global__ void __launch_bounds__(256) softmax_ctx(
    float* __restrict__ attn, const float* __restrict__ V, float* __restrict__ ctx)
{
    extern __shared__ float sm[];
    float* Ps    = sm;                       // 128 x PSTR
    float* Vs    = Ps + 128 * PSTR;          // CHUNK x VSTR
    float* m_row = Vs + CHUNK * VSTR;        // 128
    float* i_row = m_row + 128;              // 128

    const int tid  = threadIdx.x;
    const int wid  = tid >> 5;
    const int lane = tid & 31;
    const int g    = lane >> 2;
    const int tg   = lane & 3;

    const int z = blockIdx.y;
    const int b = z / HH, h = z % HH;
    const int row0 = blockIdx.x * 128;
    float* Sb = attn + (size_t)z * SS * SS + (size_t)row0 * SS;
    const size_t vbase = (size_t)b * SS * DD + (size_t)h * DK;

    // ---- pass 1: per-row max then sum (8 lanes per row) ----
#pragma unroll
    for (int rr = 0; rr < 4; rr++) {
        int row = rr * 32 + wid * 4 + (lane >> 3);
        const float4* p4 = (const float4*)(Sb + (size_t)row * SS);
        int l8 = lane & 7;
        float m = -3.0e38f;
#pragma unroll 8
        for (int j = 0; j < 64; j++) {
            float4 v = p4[l8 + j * 8];
            m = fmaxf(m, fmaxf(fmaxf(v.x, v.y), fmaxf(v.z, v.w)));
        }
        m = fmaxf(m, __shfl_xor_sync(0xffffffffu, m, 1));
        m = fmaxf(m, __shfl_xor_sync(0xffffffffu, m, 2));
        m = fmaxf(m, __shfl_xor_sync(0xffffffffu, m, 4));
        float s = 0.f;
#pragma unroll 8
        for (int j = 0; j < 64; j++) {
            float4 v = p4[l8 + j * 8];
            s += __expf(v.x - m) + __expf(v.y - m) + __expf(v.z - m) + __expf(v.w - m);
        }
        s += __shfl_xor_sync(0xffffffffu, s, 1);
        s += __shfl_xor_sync(0xffffffffu, s, 2);
        s += __shfl_xor_sync(0xffffffffu, s, 4);
        if (l8 == 0) { m_row[row] = m; i_row[row] = 1.0f / s; }
    }
    __syncthreads();

    // ---- pass 2: normalize+round+write attn, MMA with V into ctx ----
    // warps: 4 row-tiles x 2 col-tiles of 32x32
    const int wm = (wid >> 1) * 32;
    const int wn = (wid & 1) * 32;
    float c[2][4][4];
#pragma unroll
    for (int mi = 0; mi < 2; mi++)
#pragma unroll
        for (int j = 0; j < 4; j++)
#pragma unroll
            for (int r = 0; r < 4; r++) c[mi][j][r] = 0.f;

    for (int cc = 0; cc < SS / CHUNK; cc++) {
        // scores chunk: 128 rows x 16 float4
#pragma unroll
        for (int i = 0; i < 8; i++) {
            int idx = tid + i * 256;
            int row = idx >> 4, cv = idx & 15;
            float4 v = *(const float4*)(Sb + (size_t)row * SS + cc * CHUNK + cv * 4);
            float m = m_row[row], inv = i_row[row];
            v.x = rtf(__expf(v.x - m) * inv);
            v.y = rtf(__expf(v.y - m) * inv);
            v.z = rtf(__expf(v.z - m) * inv);
            v.w = rtf(__expf(v.w - m) * inv);
            *(float4*)(Sb + (size_t)row * SS + cc * CHUNK + cv * 4) = v;
            *(float4*)&Ps[row * PSTR + cv * 4] = v;
        }
        // V chunk: CHUNK rows x 16 float4
#pragma unroll
        for (int i = 0; i < 4; i++) {
            int idx = tid + i * 256;
            int row = idx >> 4, cv = idx & 15;
            float4 v = *(const float4*)(V + vbase + (size_t)(cc * CHUNK + row) * DD + cv * 4);
            *(float4*)&Vs[row * VSTR + cv * 4] = v;
        }
        __syncthreads();

#pragma unroll
        for (int kk = 0; kk < CHUNK / 8; kk++) {
            const int ks = kk * 8;
            uint32_t af[2][4], bf[4][2];
#pragma unroll
            for (int mi = 0; mi < 2; mi++) {
                int m = wm + mi * 16 + g;
                float2 p0 = *(const float2*)&Ps[m * PSTR + ks + 2 * tg];
                float2 p1 = *(const float2*)&Ps[(m + 8) * PSTR + ks + 2 * tg];
                af[mi][0] = __float_as_uint(p0.x);
                af[mi][1] = __float_as_uint(p1.x);
                af[mi][2] = __float_as_uint(p0.y);
                af[mi][3] = __float_as_uint(p1.y);
            }
#pragma unroll
            for (int j = 0; j < 4; j++) {
                int n = wn + j * 8 + g;
                bf[j][0] = __float_as_uint(Vs[(ks + 2 * tg)     * VSTR + n]);
                bf[j][1] = __float_as_uint(Vs[(ks + 2 * tg + 1) * VSTR + n]);
            }
#pragma unroll
            for (int mi = 0; mi < 2; mi++)
#pragma unroll
                for (int j = 0; j < 4; j++) mma8(c[mi][j], af[mi], bf[j]);
        }
        __syncthreads();
    }

    // write ctx (tf32-rounded; feeds Wo GEMM)
#pragma unroll
    for (int mi = 0; mi < 2; mi++) {
        int r0 = row0 + wm + mi * 16 + g;
#pragma unroll
        for (int j = 0; j < 4; j++) {
            int col = wn + j * 8 + tg * 2;
            *(float2*)(ctx + vbase + (size_t)r0 * DD + col) =
                make_float2(rtf(c[mi][j][0]), rtf(c[mi][j][1]));
            *(float2*)(ctx + vbase + (size_t)(r0 + 8) * DD + col) =
                make_float2(rtf(c[mi][j][2]), rtf(c[mi][j][3]));
        }
    }
}
#define SMCTX_BYTES ((128 * PSTR + CHUNK * VSTR + 256) * 4)

// ---------------- residual + layernorm, one block per row ---------------------
__global__ void add_ln_kernel(const float* __restrict__ x, const float* __restrict__ y,
                              const float* __restrict__ g, const float* __restrict__ be,
                              float* __restrict__ out, int rnd)
{
    size_t row = blockIdx.x;
    const float* px = x + row * DD;
    const float* py = y + row * DD;
    float* po = out + row * DD;
    int t = threadIdx.x;
    __shared__ float red[256];

    float a0 = px[t]       + py[t];
    float a1 = px[t + 256] + py[t + 256];
    float a2 = px[t + 512] + py[t + 512];

    red[t] = a0 + a1 + a2; __syncthreads();
    for (int s = 128; s > 0; s >>= 1) { if (t < s) red[t] += red[t + s]; __syncthreads(); }
    float mean = red[0] * (1.0f / DD); __syncthreads();

    float d0 = a0 - mean, d1 = a1 - mean, d2 = a2 - mean;
    red[t] = d0 * d0 + d1 * d1 + d2 * d2; __syncthreads();
    for (int s = 128; s > 0; s >>= 1) { if (t < s) red[t] += red[t + s]; __syncthreads(); }
    float rstd = rsqrtf(red[0] * (1.0f / DD) + 1e-5f);

    float o0 = d0 * rstd * g[t]       + be[t];
    float o1 = d1 * rstd * g[t + 256] + be[t + 256];
    float o2 = d2 * rstd * g[t + 512] + be[t + 512];
    if (rnd) { o0 = rtf(o0); o1 = rtf(o1); o2 = rtf(o2); }
    po[t] = o0; po[t + 256] = o1; po[t + 512] = o2;
}

// ---------------- launcher ----------------------------------------------------
extern "C" void kernel_launch(void* const* d_in, const int* in_sizes, int n_in,
                              void* d_out, int out_size)
{
    const float* x   = (const float*)d_in[0];
    const float* Wq  = (const float*)d_in[1];
    const float* bq  = (const float*)d_in[2];
    const float* Wk  = (const float*)d_in[3];
    const float* bk  = (const float*)d_in[4];
    const float* Wv  = (const float*)d_in[5];
    const float* bv  = (const float*)d_in[6];
    const float* Wo  = (const float*)d_in[7];
    const float* bo  = (const float*)d_in[8];
    const float* W1  = (const float*)d_in[9];
    const float* b1  = (const float*)d_in[10];
    const float* W2  = (const float*)d_in[11];
    const float* b2  = (const float*)d_in[12];
    const float* g1  = (const float*)d_in[13];
    const float* be1 = (const float*)d_in[14];
    const float* g2  = (const float*)d_in[15];
    const float* be2 = (const float*)d_in[16];

    float* out  = (float*)d_out;                 // x2: [2,2048,768]
    float* attn = out + X2_ELEMS;                // attn_weights: [2,12,2048,2048]

    float *Qp, *Kp, *Vp, *Cp, *X1p, *T2p, *FFp;
    float *xr, *Wqr, *Wkr, *Wvr, *Wor, *W1r, *W2r;
    cudaGetSymbolAddress((void**)&Qp,  g_Q);
    cudaGetSymbolAddress((void**)&Kp,  g_K);
    cudaGetSymbolAddress((void**)&Vp,  g_V);
    cudaGetSymbolAddress((void**)&Cp,  g_ctx);
    cudaGetSymbolAddress((void**)&X1p, g_x1);
    cudaGetSymbolAddress((void**)&T2p, g_t2);
    cudaGetSymbolAddress((void**)&FFp, g_ff);
    cudaGetSymbolAddress((void**)&xr,  g_xr);
    cudaGetSymbolAddress((void**)&Wqr, g_Wqr);
    cudaGetSymbolAddress((void**)&Wkr, g_Wkr);
    cudaGetSymbolAddress((void**)&Wvr, g_Wvr);
    cudaGetSymbolAddress((void**)&Wor, g_Wor);
    cudaGetSymbolAddress((void**)&W1r, g_W1r);
    cudaGetSymbolAddress((void**)&W2r, g_W2r);

    static int smem_set = 0;
    if (!smem_set) {
        cudaFuncSetAttribute(softmax_ctx, cudaFuncAttributeMaxDynamicSharedMemorySize,
                             SMCTX_BYTES);
        smem_set = 1;
    }

    const long long Z0 = 0;

    // pre-round all GEMM inputs to tf32 (RNA), one merged launch
    {
        constexpr int TOT4 = MM*DD/4 + 4*(DD*DD/4) + 2*(DD*DFF/4);
        round_all<<<(TOT4 + 255) / 256, 256>>>(
            (const float4*)x,  (float4*)xr,
            (const float4*)Wq, (float4*)Wqr,
            (const float4*)Wk, (float4*)Wkr,
            (const float4*)Wv, (float4*)Wvr,
            (const float4*)Wo, (float4*)Wor,
            (const float4*)W1, (float4*)W1r,
            (const float4*)W2, (float4*)W2r);
    }

    // merged Q/K/V projections, outputs rounded
    gemm_tf32<128,128,64,32,false,true><<<dim3(DD/128, MM/128, 3), 256>>>(
        xr, Wqr, bq, Qp, Wkr, bk, Kp, Wvr, bv, Vp,
        DD, DD, DD, DD, Z0,Z0,Z0,Z0,Z0,Z0, 1.f, 0, 1);

    // scores = Q @ K^T / 8 -> output attn region
    scores_k64<<<dim3(SS/128, SS/128, BB*HH), 256>>>(Qp, Kp, attn);

    // fused softmax (in place, rounded) + ctx = attn @ V
    softmax_ctx<<<dim3(SS/128, BB*HH), 256, SMCTX_BYTES>>>(attn, Vp, Cp);

    // attn_out = ctx @ Wo + bo (fp32 out)
    gemm_tf32<128,128,64,32,false,false><<<dim3(DD/128, MM/128, 1), 256>>>(
        Cp, Wor, bo, T2p, nullptr, nullptr, nullptr, nullptr, nullptr, nullptr,
        DD, DD, DD, DD, Z0,Z0,Z0,Z0,Z0,Z0, 1.f, 0, 0);

    // x1 = LN(x + attn_out), rounded (feeds FFN1)
    add_ln_kernel<<<MM, 256>>>(x, T2p, g1, be1, X1p, 1);

    // ff = relu(x1 @ W1 + b1) rounded; ff2 = ff @ W2 + b2 fp32
    gemm_tf32<128,128,64,32,false,false><<<dim3(DFF/128, MM/128, 1), 256>>>(
        X1p, W1r, b1, FFp, nullptr, nullptr, nullptr, nullptr, nullptr, nullptr,
        DD, DD, DFF, DFF, Z0,Z0,Z0,Z0,Z0,Z0, 1.f, 1, 1);
    gemm_tf32<128,128,64,32,false,false><<<dim3(DD/128, MM/128, 1), 256>>>(
        FFp, W2r, b2, T2p, nullptr, nullptr, nullptr, nullptr, nullptr, nullptr,
        DFF, DFF, DD, DD, Z0,Z0,Z0,Z0,Z0,Z0, 1.f, 0, 0);

    // x2 = LN(x1 + ff2) -> output (fp32)
    add_ln_kernel<<<MM, 256>>>(X1p, T2p, g2, be2, out, 0);
}

// round 7
// speedup vs baseline: 1.0609x; 1.0609x over previous
#include <cuda_runtime.h>
#include <cstdint>
#include <cstddef>

#define BB 2
#define SS 2048
#define DD 768
#define HH 12
#define DK 64
#define DFF 3072
#define MM (BB*SS)                 // 4096
#define X2_ELEMS ((size_t)MM*DD)   // 3145728
#define NBLK 16                    // SS/128 col blocks per row

// ---------------- scratch (static device globals; no allocation) -------------
__device__ float g_Q[(size_t)MM*DD];
__device__ float g_K[(size_t)MM*DD];
__device__ float g_V[(size_t)MM*DD];
__device__ float g_ctx[(size_t)MM*DD];
__device__ float g_x1[(size_t)MM*DD];
__device__ float g_t2[(size_t)MM*DD];
__device__ float g_ff[(size_t)MM*DFF];
// rounded copies of GEMM inputs
__device__ float g_xr[(size_t)MM*DD];
__device__ float g_Wqr[(size_t)DD*DD];
__device__ float g_Wkr[(size_t)DD*DD];
__device__ float g_Wvr[(size_t)DD*DD];
__device__ float g_Wor[(size_t)DD*DD];
__device__ float g_W1r[(size_t)DD*DFF];
__device__ float g_W2r[(size_t)DFF*DD];
// softmax partials / row stats
__device__ float g_pm[(size_t)BB*HH*NBLK*SS];
__device__ float g_ps[(size_t)BB*HH*NBLK*SS];
__device__ float g_rm[(size_t)BB*HH*SS];
__device__ float g_ri[(size_t)BB*HH*SS];

// ---------------- helpers ----------------------------------------------------
__device__ __forceinline__ float rtf(float v) {       // round-to-nearest tf32
    uint32_t r;
    asm("cvt.rna.tf32.f32 %0, %1;" : "=r"(r) : "f"(v));
    return __uint_as_float(r);
}

__device__ __forceinline__ void mma8(float* c, const uint32_t* a, const uint32_t* b) {
    asm volatile(
        "mma.sync.aligned.m16n8k8.row.col.f32.tf32.tf32.f32 "
        "{%0,%1,%2,%3},{%4,%5,%6,%7},{%8,%9},{%0,%1,%2,%3};\n"
        : "+f"(c[0]), "+f"(c[1]), "+f"(c[2]), "+f"(c[3])
        : "r"(a[0]), "r"(a[1]), "r"(a[2]), "r"(a[3]), "r"(b[0]), "r"(b[1]));
}

__device__ __forceinline__ void cp16(uint32_t smem_addr, const void* gptr) {
    asm volatile("cp.async.cg.shared.global [%0], [%1], 16;\n"
                 :: "r"(smem_addr), "l"(gptr));
}
__device__ __forceinline__ void cp_commit() {
    asm volatile("cp.async.commit_group;\n" ::: "memory");
}
template<int N>
__device__ __forceinline__ void cp_wait() {
    asm volatile("cp.async.wait_group %0;\n" :: "n"(N) : "memory");
}

// ---------------- merged elementwise tf32 pre-round (7 segments) --------------
__global__ void round_all(
    const float4* __restrict__ x,  float4* __restrict__ xr,
    const float4* __restrict__ wq, float4* __restrict__ wqr,
    const float4* __restrict__ wk, float4* __restrict__ wkr,
    const float4* __restrict__ wv, float4* __restrict__ wvr,
    const float4* __restrict__ wo, float4* __restrict__ wor,
    const float4* __restrict__ w1, float4* __restrict__ w1r,
    const float4* __restrict__ w2, float4* __restrict__ w2r)
{
    constexpr int SX = MM*DD/4, SW = DD*DD/4, SF = DD*DFF/4;
    int i = blockIdx.x * blockDim.x + threadIdx.x;
    const float4* in; float4* out; int off;
    if      (i < SX)                  { in = x;  out = xr;  off = 0; }
    else if (i < SX + SW)             { in = wq; out = wqr; off = SX; }
    else if (i < SX + 2*SW)           { in = wk; out = wkr; off = SX + SW; }
    else if (i < SX + 3*SW)           { in = wv; out = wvr; off = SX + 2*SW; }
    else if (i < SX + 4*SW)           { in = wo; out = wor; off = SX + 3*SW; }
    else if (i < SX + 4*SW + SF)      { in = w1; out = w1r; off = SX + 4*SW; }
    else if (i < SX + 4*SW + 2*SF)    { in = w2; out = w2r; off = SX + 4*SW + SF; }
    else return;
    int j = i - off;
    float4 v = in[j];
    v.x = rtf(v.x); v.y = rtf(v.y); v.z = rtf(v.z); v.w = rtf(v.w);
    out[j] = v;
}

// ---------------- generic TF32 tensor-core GEMM (cp.async double buffer) -----
template<int BM, int BN, int WM, int WN, bool TB, bool QKV>
__global__ void __launch_bounds__(256, 2) gemm_tf32(
    const float* __restrict__ A,
    const float* __restrict__ B0, const float* __restrict__ bias0, float* __restrict__ C0,
    const float* __restrict__ B1p, const float* __restrict__ bias1p, float* __restrict__ C1p,
    const float* __restrict__ B2p, const float* __restrict__ bias2p, float* __restrict__ C2p,
    int K, int lda, int ldb, int ldc,
    long long sA1, long long sA2, long long sB1, long long sB2,
    long long sC1, long long sC2, float alpha, int relu, int rnd)
{
    constexpr int MI  = WM / 16;
    constexpr int NJ  = WN / 8;
    constexpr int WGN = BN / WN;
    constexpr int ASTR = 40;
    constexpr int BSTR = TB ? 40 : (BN + 4);
    constexpr int ASZ  = BM * ASTR;
    constexpr int BSZ  = TB ? (BN * 40) : (32 * (BN + 4));
    constexpr int NAV  = BM * 8 / 256;
    constexpr int NBV  = TB ? (BN * 8 / 256) : (8 * BN / 256);

    __shared__ float As[2 * ASZ];
    __shared__ float Bs[2 * BSZ];

    const int tid  = threadIdx.x;
    const int wid  = tid >> 5;
    const int lane = tid & 31;
    const int g    = lane >> 2;
    const int tg   = lane & 3;
    const int wm   = (wid / WGN) * WM;
    const int wn   = (wid % WGN) * WN;

    const float* B    = B0;
    const float* bias = bias0;
    float*       C    = C0;
    long long zb = 0, zh = 0;
    if (QKV) {
        int z = blockIdx.z;
        if (z == 1) { B = B1p; bias = bias1p; C = C1p; }
        else if (z == 2) { B = B2p; bias = bias2p; C = C2p; }
    } else {
        int z = blockIdx.z;
        zb = z / HH; zh = z % HH;
    }

    const float* Ab = A + zb * sA1 + zh * sA2 + (size_t)blockIdx.y * BM * lda;
    const float* Bb = B + zb * sB1 + zh * sB2 +
                      (TB ? (size_t)blockIdx.x * BN * ldb : (size_t)blockIdx.x * BN);
    float* Cb = C + zb * sC1 + zh * sC2 +
                (size_t)blockIdx.y * BM * ldc + (size_t)blockIdx.x * BN;

    const uint32_t sA_base = (uint32_t)__cvta_generic_to_shared(As);
    const uint32_t sB_base = (uint32_t)__cvta_generic_to_shared(Bs);

    auto issue = [&](int k0, int st) {
        uint32_t abuf = sA_base + st * ASZ * 4;
#pragma unroll
        for (int i = 0; i < NAV; i++) {
            int idx = tid + i * 256;
            int m = idx >> 3, cv = idx & 7;
            cp16(abuf + (m * ASTR + cv * 4) * 4,
                 Ab + (size_t)m * lda + k0 + cv * 4);
        }
        uint32_t bbuf = sB_base + st * BSZ * 4;
#pragma unroll
        for (int i = 0; i < NBV; i++) {
            int idx = tid + i * 256;
            if (TB) {
                int n = idx >> 3, cv = idx & 7;
                cp16(bbuf + (n * BSTR + cv * 4) * 4,
                     Bb + (size_t)n * ldb + k0 + cv * 4);
            } else {
                int r = idx / (BN / 4), cv = idx % (BN / 4);
                cp16(bbuf + (r * BSTR + cv * 4) * 4,
                     Bb + (size_t)(k0 + r) * ldb + cv * 4);
            }
        }
        cp_commit();
    };

    float c[MI][NJ][4];
#pragma unroll
    for (int mi = 0; mi < MI; mi++)
#pragma unroll
        for (int j = 0; j < NJ; j++)
#pragma unroll
            for (int r = 0; r < 4; r++) c[mi][j][r] = 0.f;

    const int nK = K / 32;
    issue(0, 0);

    for (int kc = 0; kc < nK; kc++) {
        const int st = kc & 1;
        if (kc + 1 < nK) {
            issue((kc + 1) * 32, st ^ 1);
            cp_wait<1>();
        } else {
            cp_wait<0>();
        }
        __syncthreads();

        const float* Ac = As + st * ASZ;
        const float* Bc = Bs + st * BSZ;
#pragma unroll
        for (int kk = 0; kk < 4; kk++) {
            const int ks = kk * 8;
            uint32_t af[MI][4], bf[NJ][2];
#pragma unroll
            for (int mi = 0; mi < MI; mi++) {
                int m = wm + mi * 16 + g;
                float2 p0 = *(const float2*)&Ac[m * ASTR + ks + 2 * tg];
                float2 p1 = *(const float2*)&Ac[(m + 8) * ASTR + ks + 2 * tg];
                af[mi][0] = __float_as_uint(p0.x);
                af[mi][1] = __float_as_uint(p1.x);
                af[mi][2] = __float_as_uint(p0.y);
                af[mi][3] = __float_as_uint(p1.y);
            }
#pragma unroll
            for (int j = 0; j < NJ; j++) {
                int n = wn + j * 8 + g;
                if (TB) {
                    float2 q = *(const float2*)&Bc[n * BSTR + ks + 2 * tg];
                    bf[j][0] = __float_as_uint(q.x);
                    bf[j][1] = __float_as_uint(q.y);
                } else {
                    bf[j][0] = __float_as_uint(Bc[(ks + 2 * tg)     * BSTR + n]);
                    bf[j][1] = __float_as_uint(Bc[(ks + 2 * tg + 1) * BSTR + n]);
                }
            }
#pragma unroll
            for (int mi = 0; mi < MI; mi++)
#pragma unroll
                for (int j = 0; j < NJ; j++) mma8(c[mi][j], af[mi], bf[j]);
        }
        __syncthreads();
    }

#pragma unroll
    for (int mi = 0; mi < MI; mi++) {
        int r0 = wm + mi * 16 + g;
#pragma unroll
        for (int j = 0; j < NJ; j++) {
            int col = wn + j * 8 + tg * 2;
            float2 bb = make_float2(0.f, 0.f);
            if (bias) bb = *(const float2*)(bias + (size_t)blockIdx.x * BN + col);
            float v0 = c[mi][j][0] * alpha + bb.x;
            float v1 = c[mi][j][1] * alpha + bb.y;
            float v2 = c[mi][j][2] * alpha + bb.x;
            float v3 = c[mi][j][3] * alpha + bb.y;
            if (relu) {
                v0 = fmaxf(v0, 0.f); v1 = fmaxf(v1, 0.f);
                v2 = fmaxf(v2, 0.f); v3 = fmaxf(v3, 0.f);
            }
            if (rnd) { v0 = rtf(v0); v1 = rtf(v1); v2 = rtf(v2); v3 = rtf(v3); }
            *(float2*)(Cb + (size_t)r0 * ldc + col)       = make_float2(v0, v1);
            *(float2*)(Cb + (size_t)(r0 + 8) * ldc + col) = make_float2(v2, v3);
        }
    }
}

// ---------------- scores + per-block softmax partials -------------------------
// Writes raw scores to attn AND per-(row, 128-col-block) (max, sumexp) partials.
__global__ void __launch_bounds__(256, 2) scores_k64(
    const float* __restrict__ Q, const float* __restrict__ Km, float* __restrict__ attn,
    float* __restrict__ pm, float* __restrict__ ps)
{
    constexpr int STR = 72;
    __shared__ float As[128 * STR];
    __shared__ float Bs[128 * STR];
    __shared__ float sm_m[128][4];
    __shared__ float sm_s[128][4];

    const int tid  = threadIdx.x;
    const int wid  = tid >> 5;
    const int lane = tid & 31;
    const int g    = lane >> 2;
    const int tg   = lane & 3;
    const int wm   = (wid >> 2) * 64;
    const int wn   = (wid & 3) * 32;

    const int z = blockIdx.z;
    const int b = z / HH, h = z % HH;
    const size_t base = (size_t)b * SS * DD + (size_t)h * DK;
    const int row0 = blockIdx.y * 128;
    const int col0 = blockIdx.x * 128;

    const uint32_t sA = (uint32_t)__cvta_generic_to_shared(As);
    const uint32_t sB = (uint32_t)__cvta_generic_to_shared(Bs);

#pragma unroll
    for (int i = 0; i < 8; i++) {
        int idx = tid + i * 256;
        int m = idx >> 4, cv = idx & 15;
        cp16(sA + (m * STR + cv * 4) * 4, Q  + base + (size_t)(row0 + m) * DD + cv * 4);
        cp16(sB + (m * STR + cv * 4) * 4, Km + base + (size_t)(col0 + m) * DD + cv * 4);
    }
    cp_commit();
    cp_wait<0>();
    __syncthreads();

    float c[4][4][4];
#pragma unroll
    for (int mi = 0; mi < 4; mi++)
#pragma unroll
        for (int j = 0; j < 4; j++)
#pragma unroll
            for (int r = 0; r < 4; r++) c[mi][j][r] = 0.f;

#pragma unroll
    for (int kk = 0; kk < 8; kk++) {
        const int ks = kk * 8;
        uint32_t af[4][4], bf[4][2];
#pragma unroll
        for (int mi = 0; mi < 4; mi++) {
            int m = wm + mi * 16 + g;
            float2 p0 = *(const float2*)&As[m * STR + ks + 2 * tg];
            float2 p1 = *(const float2*)&As[(m + 8) * STR + ks + 2 * tg];
            af[mi][0] = __float_as_uint(p0.x);
            af[mi][1] = __float_as_uint(p1.x);
            af[mi][2] = __float_as_uint(p0.y);
            af[mi][3] = __float_as_uint(p1.y);
        }
#pragma unroll
        for (int j = 0; j < 4; j++) {
            int n = wn + j * 8 + g;
            float2 q = *(const float2*)&Bs[n * STR + ks + 2 * tg];
            bf[j][0] = __float_as_uint(q.x);
            bf[j][1] = __float_as_uint(q.y);
        }
#pragma unroll
        for (int mi = 0; mi < 4; mi++)
#pragma unroll
            for (int j = 0; j < 4; j++) mma8(c[mi][j], af[mi], bf[j]);
    }

    // scale + write + per-row partial reduction over this 128-col block
    float* out = attn + (size_t)z * SS * SS;
#pragma unroll
    for (int mi = 0; mi < 4; mi++) {
        int r0 = row0 + wm + mi * 16 + g;
#pragma unroll
        for (int j = 0; j < 4; j++) {
#pragma unroll
            for (int r = 0; r < 4; r++) c[mi][j][r] *= 0.125f;
            int col = col0 + wn + j * 8 + tg * 2;
            *(float2*)(out + (size_t)r0 * SS + col)       = make_float2(c[mi][j][0], c[mi][j][1]);
            *(float2*)(out + (size_t)(r0 + 8) * SS + col) = make_float2(c[mi][j][2], c[mi][j][3]);
        }
#pragma unroll
        for (int half = 0; half < 2; half++) {
            float m = -3.0e38f;
#pragma unroll
            for (int j = 0; j < 4; j++)
                m = fmaxf(m, fmaxf(c[mi][j][half*2], c[mi][j][half*2+1]));
            m = fmaxf(m, __shfl_xor_sync(0xffffffffu, m, 1));
            m = fmaxf(m, __shfl_xor_sync(0xffffffffu, m, 2));
            float s = 0.f;
#pragma unroll
            for (int j = 0; j < 4; j++)
                s += __expf(c[mi][j][half*2] - m) + __expf(c[mi][j][half*2+1] - m);
            s += __shfl_xor_sync(0xffffffffu, s, 1);
            s += __shfl_xor_sync(0xffffffffu, s, 2);
            if (tg == 0) {
                int row = wm + mi * 16 + g + half * 8;
                sm_m[row][wid & 3] = m;
                sm_s[row][wid & 3] = s;
            }
        }
    }
    __syncthreads();

    if (tid < 128) {
        float m0 = sm_m[tid][0], m1 = sm_m[tid][1], m2 = sm_m[tid][2], m3 = sm_m[tid][3];
        float m = fmaxf(fmaxf(m0, m1), fmaxf(m2, m3));
        float s = sm_s[tid][0] * __expf(m0 - m) + sm_s[tid][1] * __expf(m1 - m)
                + sm_s[tid][2] * __expf(m2 - m) + sm_s[tid][3] * __expf(m3 - m);
        size_t pidx = ((size_t)z * NBLK + blockIdx.x) * SS + row0 + tid;
        pm[pidx] = m;
        ps[pidx] = s;
    }
}

// ---------------- combine partials -> per-row (max, 1/sum) --------------------
__global__ void rowstats(const float* __restrict__ pm, const float* __restrict__ ps,
                         float* __restrict__ rm, float* __restrict__ ri)
{
    int idx = blockIdx.x * blockDim.x + threadIdx.x;   // z*SS + row
    if (idx >= BB * HH * SS) return;
    int z = idx / SS, row = idx % SS;
    float m = -3.0e38f;
    float mv[NBLK];
#pragma unroll
    for (int blk = 0; blk < NBLK; blk++) {
        mv[blk] = pm[((size_t)z * NBLK + blk) * SS + row];
        m = fmaxf(m, mv[blk]);
    }
    float s = 0.f;
#pragma unroll
    for (int blk = 0; blk < NBLK; blk++)
        s += ps[((size_t)z * NBLK + blk) * SS + row] * __expf(mv[blk] - m);
    rm[idx] = m;
    ri[idx] = 1.0f / s;
}

// ---------------- pv: normalize attn in place + ctx = P @ V -------------------
// 64 q-rows per block, single streaming pass over scores.
#define PR 64
#define PSTR 72
#define VSTR 68
__global__ void __launch_bounds__(256) pv_kernel(
    float* __restrict__ attn, const float* __restrict__ V,
    const float* __restrict__ rm, const float* __restrict__ ri,
    float* __restrict__ ctx)
{
    __shared__ float Ps[PR * PSTR];
    __shared__ float Vs[64 * VSTR];
    __shared__ float sm_rm[PR];
    __shared__ float sm_ri[PR];

    const int tid  = threadIdx.x;
    const int wid  = tid >> 5;
    const int lane = tid & 31;
    const int g    = lane >> 2;
    const int tg   = lane & 3;
    const int wm   = (wid >> 1) * 16;   // 4 row tiles of 16
    const int wn   = (wid & 1) * 32;    // 2 col tiles of 32

    const int z = blockIdx.y;
    const int b = z / HH, h = z % HH;
    const int row0 = blockIdx.x * PR;
    float* Sb = attn + (size_t)z * SS * SS + (size_t)row0 * SS;
    const size_t vbase = (size_t)b * SS * DD + (size_t)h * DK;

    if (tid < PR) {
        sm_rm[tid] = rm[(size_t)z * SS + row0 + tid];
        sm_ri[tid] = ri[(size_t)z * SS + row0 + tid];
    }
    __syncthreads();

    float c[4][4];
#pragma unroll
    for (int j = 0; j < 4; j++)
#pragma unroll
        for (int r = 0; r < 4; r++) c[j][r] = 0.f;

    for (int cc = 0; cc < SS / 64; cc++) {
        // normalize + write attn + stage P (64x64)
#pragma unroll
        for (int i = 0; i < 4; i++) {
            int idx = tid + i * 256;
            int row = idx >> 4, cv = idx & 15;
            float m = sm_rm[row], inv = sm_ri[row];
            float* p = Sb + (size_t)row * SS + cc * 64 + cv * 4;
            float4 v = *(const float4*)p;
            v.x = rtf(__expf(v.x - m) * inv);
            v.y = rtf(__expf(v.y - m) * inv);
            v.z = rtf(__expf(v.z - m) * inv);
            v.w = rtf(__expf(v.w - m) * inv);
            *(float4*)p = v;
            *(float4*)&Ps[row * PSTR + cv * 4] = v;
        }
        // stage V chunk (64x64)
#pragma unroll
        for (int i = 0; i < 4; i++) {
            int idx = tid + i * 256;
            int row = idx >> 4, cv = idx & 15;
            *(float4*)&Vs[row * VSTR + cv * 4] =
                *(const float4*)(V + vbase + (size_t)(cc * 64 + row) * DD + cv * 4);
        }
        __syncthreads();

#pragma unroll
        for (int kk = 0; kk < 8; kk++) {
            const int ks = kk * 8;
            uint32_t af[4], bf[4][2];
            {
                int m = wm + g;
                float2 p0 = *(const float2*)&Ps[m * PSTR + ks + 2 * tg];
                float2 p1 = *(const float2*)&Ps[(m + 8) * PSTR + ks + 2 * tg];
                af[0] = __float_as_uint(p0.x);
                af[1] = __float_as_uint(p1.x);
                af[2] = __float_as_uint(p0.y);
                af[3] = __float_as_uint(p1.y);
            }
#pragma unroll
            for (int j = 0; j < 4; j++) {
                int n = wn + j * 8 + g;
                bf[j][0] = __float_as_uint(Vs[(ks + 2 * tg)     * VSTR + n]);
                bf[j][1] = __float_as_uint(Vs[(ks + 2 * tg + 1) * VSTR + n]);
            }
#pragma unroll
            for (int j = 0; j < 4; j++) mma8(c[j], af, bf[j]);
        }
        __syncthreads();
    }

    // write ctx (tf32-rounded; feeds Wo GEMM)
    int r0 = row0 + wm + g;
#pragma unroll
    for (int j = 0; j < 4; j++) {
        int col = wn + j * 8 + tg * 2;
        *(float2*)(ctx + vbase + (size_t)r0 * DD + col) =
            make_float2(rtf(c[j][0]), rtf(c[j][1]));
        *(float2*)(ctx + vbase + (size_t)(r0 + 8) * DD + col) =
            make_float2(rtf(c[j][2]), rtf(c[j][3]));
    }
}

// ---------------- residual + layernorm, one block per row ---------------------
__global__ void add_ln_kernel(const float* __restrict__ x, const float* __restrict__ y,
                              const float* __restrict__ g, const float* __restrict__ be,
                              float* __restrict__ out, int rnd)
{
    size_t row = blockIdx.x;
    const float* px = x + row * DD;
    const float* py = y + row * DD;
    float* po = out + row * DD;
    int t = threadIdx.x;
    __shared__ float red[256];

    float a0 = px[t]       + py[t];
    float a1 = px[t + 256] + py[t + 256];
    float a2 = px[t + 512] + py[t + 512];

    red[t] = a0 + a1 + a2; __syncthreads();
    for (int s = 128; s > 0; s >>= 1) { if (t < s) red[t] += red[t + s]; __syncthreads(); }
    float mean = red[0] * (1.0f / DD); __syncthreads();

    float d0 = a0 - mean, d1 = a1 - mean, d2 = a2 - mean;
    red[t] = d0 * d0 + d1 * d1 + d2 * d2; __syncthreads();
    for (int s = 128; s > 0; s >>= 1) { if (t < s) red[t] += red[t + s]; __syncthreads(); }
    float rstd = rsqrtf(red[0] * (1.0f / DD) + 1e-5f);

    float o0 = d0 * rstd * g[t]       + be[t];
    float o1 = d1 * rstd * g[t + 256] + be[t + 256];
    float o2 = d2 * rstd * g[t + 512] + be[t + 512];
    if (rnd) { o0 = rtf(o0); o1 = rtf(o1); o2 = rtf(o2); }
    po[t] = o0; po[t + 256] = o1; po[t + 512] = o2;
}

// ---------------- launcher ----------------------------------------------------
extern "C" void kernel_launch(void* const* d_in, const int* in_sizes, int n_in,
                              void* d_out, int out_size)
{
    const float* x   = (const float*)d_in[0];
    const float* Wq  = (const float*)d_in[1];
    const float* bq  = (const float*)d_in[2];
    const float* Wk  = (const float*)d_in[3];
    const float* bk  = (const float*)d_in[4];
    const float* Wv  = (const float*)d_in[5];
    const float* bv  = (const float*)d_in[6];
    const float* Wo  = (const float*)d_in[7];
    const float* bo  = (const float*)d_in[8];
    const float* W1  = (const float*)d_in[9];
    const float* b1  = (const float*)d_in[10];
    const float* W2  = (const float*)d_in[11];
    const float* b2  = (const float*)d_in[12];
    const float* g1  = (const float*)d_in[13];
    const float* be1 = (const float*)d_in[14];
    const float* g2  = (const float*)d_in[15];
    const float* be2 = (const float*)d_in[16];

    float* out  = (float*)d_out;                 // x2: [2,2048,768]
    float* attn = out + X2_ELEMS;                // attn_weights: [2,12,2048,2048]

    float *Qp, *Kp, *Vp, *Cp, *X1p, *T2p, *FFp;
    float *xr, *Wqr, *Wkr, *Wvr, *Wor, *W1r, *W2r;
    float *pmp, *psp, *rmp, *rip;
    cudaGetSymbolAddress((void**)&Qp,  g_Q);
    cudaGetSymbolAddress((void**)&Kp,  g_K);
    cudaGetSymbolAddress((void**)&Vp,  g_V);
    cudaGetSymbolAddress((void**)&Cp,  g_ctx);
    cudaGetSymbolAddress((void**)&X1p, g_x1);
    cudaGetSymbolAddress((void**)&T2p, g_t2);
    cudaGetSymbolAddress((void**)&FFp, g_ff);
    cudaGetSymbolAddress((void**)&xr,  g_xr);
    cudaGetSymbolAddress((void**)&Wqr, g_Wqr);
    cudaGetSymbolAddress((void**)&Wkr, g_Wkr);
    cudaGetSymbolAddress((void**)&Wvr, g_Wvr);
    cudaGetSymbolAddress((void**)&Wor, g_Wor);
    cudaGetSymbolAddress((void**)&W1r, g_W1r);
    cudaGetSymbolAddress((void**)&W2r, g_W2r);
    cudaGetSymbolAddress((void**)&pmp, g_pm);
    cudaGetSymbolAddress((void**)&psp, g_ps);
    cudaGetSymbolAddress((void**)&rmp, g_rm);
    cudaGetSymbolAddress((void**)&rip, g_ri);

    const long long Z0 = 0;

    // pre-round all GEMM inputs to tf32 (RNA), one merged launch
    {
        constexpr int TOT4 = MM*DD/4 + 4*(DD*DD/4) + 2*(DD*DFF/4);
        round_all<<<(TOT4 + 255) / 256, 256>>>(
            (const float4*)x,  (float4*)xr,
            (const float4*)Wq, (float4*)Wqr,
            (const float4*)Wk, (float4*)Wkr,
            (const float4*)Wv, (float4*)Wvr,
            (const float4*)Wo, (float4*)Wor,
            (const float4*)W1, (float4*)W1r,
            (const float4*)W2, (float4*)W2r);
    }

    // merged Q/K/V projections, outputs rounded
    gemm_tf32<128,128,64,32,false,true><<<dim3(DD/128, MM/128, 3), 256>>>(
        xr, Wqr, bq, Qp, Wkr, bk, Kp, Wvr, bv, Vp,
        DD, DD, DD, DD, Z0,Z0,Z0,Z0,Z0,Z0, 1.f, 0, 1);

    // scores (raw) + per-block softmax partials
    scores_k64<<<dim3(SS/128, SS/128, BB*HH), 256>>>(Qp, Kp, attn, pmp, psp);

    // combine partials into per-row stats
    rowstats<<<(BB*HH*SS + 255) / 256, 256>>>(pmp, psp, rmp, rip);

    // normalize attn in place (single pass) + ctx = P @ V
    pv_kernel<<<dim3(SS/PR, BB*HH), 256>>>(attn, Vp, rmp, rip, Cp);

    // attn_out = ctx @ Wo + bo (fp32 out)
    gemm_tf32<128,128,64,32,false,false><<<dim3(DD/128, MM/128, 1), 256>>>(
        Cp, Wor, bo, T2p, nullptr, nullptr, nullptr, nullptr, nullptr, nullptr,
        DD, DD, DD, DD, Z0,Z0,Z0,Z0,Z0,Z0, 1.f, 0, 0);

    // x1 = LN(x + attn_out), rounded (feeds FFN1)
    add_ln_kernel<<<MM, 256>>>(x, T2p, g1, be1, X1p, 1);

    // ff = relu(x1 @ W1 + b1) rounded; ff2 = ff @ W2 + b2 fp32
    gemm_tf32<128,128,64,32,false,false><<<dim3(DFF/128, MM/128, 1), 256>>>(
        X1p, W1r, b1, FFp, nullptr, nullptr, nullptr, nullptr, nullptr, nullptr,
        DD, DD, DFF, DFF, Z0,Z0,Z0,Z0,Z0,Z0, 1.f, 1, 1);
    gemm_tf32<128,128,64,32,false,false><<<dim3(DD/128, MM/128, 1), 256>>>(
        FFp, W2r, b2, T2p, nullptr, nullptr, nullptr, nullptr, nullptr, nullptr,
        DFF, DFF, DD, DD, Z0,Z0,Z0,Z0,Z0,Z0, 1.f, 0, 0);

    // x2 = LN(x1 + ff2) -> output (fp32)
    add_ln_kernel<<<MM, 256>>>(X1p, T2p, g2, be2, out, 0);
}

// round 8
// speedup vs baseline: 1.1106x; 1.0468x over previous
#include <cuda_runtime.h>
#include <cstdint>
#include <cstddef>

#define BB 2
#define SS 2048
#define DD 768
#define HH 12
#define DK 64
#define DFF 3072
#define MM (BB*SS)                 // 4096
#define X2_ELEMS ((size_t)MM*DD)   // 3145728
#define NBLK 16                    // SS/128 col blocks per row

// ---------------- scratch (static device globals; no allocation) -------------
__device__ float g_Q[(size_t)MM*DD];
__device__ float g_K[(size_t)MM*DD];
__device__ float g_V[(size_t)MM*DD];
__device__ float g_ctx[(size_t)MM*DD];
__device__ float g_x1[(size_t)MM*DD];
__device__ float g_t2[(size_t)MM*DD];
__device__ float g_ff[(size_t)MM*DFF];
// rounded copies of GEMM inputs
__device__ float g_xr[(size_t)MM*DD];
__device__ float g_Wqr[(size_t)DD*DD];
__device__ float g_Wkr[(size_t)DD*DD];
__device__ float g_Wvr[(size_t)DD*DD];
__device__ float g_Wor[(size_t)DD*DD];
__device__ float g_W1r[(size_t)DD*DFF];
__device__ float g_W2r[(size_t)DFF*DD];
// softmax partials / row stats
__device__ float g_pm[(size_t)BB*HH*NBLK*SS];
__device__ float g_ps[(size_t)BB*HH*NBLK*SS];
__device__ float g_rm[(size_t)BB*HH*SS];
__device__ float g_ri[(size_t)BB*HH*SS];

// ---------------- helpers ----------------------------------------------------
__device__ __forceinline__ float rtf(float v) {       // round-to-nearest tf32
    uint32_t r;
    asm("cvt.rna.tf32.f32 %0, %1;" : "=r"(r) : "f"(v));
    return __uint_as_float(r);
}

__device__ __forceinline__ void mma8(float* c, const uint32_t* a, const uint32_t* b) {
    asm volatile(
        "mma.sync.aligned.m16n8k8.row.col.f32.tf32.tf32.f32 "
        "{%0,%1,%2,%3},{%4,%5,%6,%7},{%8,%9},{%0,%1,%2,%3};\n"
        : "+f"(c[0]), "+f"(c[1]), "+f"(c[2]), "+f"(c[3])
        : "r"(a[0]), "r"(a[1]), "r"(a[2]), "r"(a[3]), "r"(b[0]), "r"(b[1]));
}

__device__ __forceinline__ void cp16(uint32_t smem_addr, const void* gptr) {
    asm volatile("cp.async.cg.shared.global [%0], [%1], 16;\n"
                 :: "r"(smem_addr), "l"(gptr));
}
__device__ __forceinline__ void cp_commit() {
    asm volatile("cp.async.commit_group;\n" ::: "memory");
}
template<int N>
__device__ __forceinline__ void cp_wait() {
    asm volatile("cp.async.wait_group %0;\n" :: "n"(N) : "memory");
}

// ---------------- merged elementwise tf32 pre-round (7 segments) --------------
__global__ void round_all(
    const float4* __restrict__ x,  float4* __restrict__ xr,
    const float4* __restrict__ wq, float4* __restrict__ wqr,
    const float4* __restrict__ wk, float4* __restrict__ wkr,
    const float4* __restrict__ wv, float4* __restrict__ wvr,
    const float4* __restrict__ wo, float4* __restrict__ wor,
    const float4* __restrict__ w1, float4* __restrict__ w1r,
    const float4* __restrict__ w2, float4* __restrict__ w2r)
{
    constexpr int SX = MM*DD/4, SW = DD*DD/4, SF = DD*DFF/4;
    int i = blockIdx.x * blockDim.x + threadIdx.x;
    const float4* in; float4* out; int off;
    if      (i < SX)                  { in = x;  out = xr;  off = 0; }
    else if (i < SX + SW)             { in = wq; out = wqr; off = SX; }
    else if (i < SX + 2*SW)           { in = wk; out = wkr; off = SX + SW; }
    else if (i < SX + 3*SW)           { in = wv; out = wvr; off = SX + 2*SW; }
    else if (i < SX + 4*SW)           { in = wo; out = wor; off = SX + 3*SW; }
    else if (i < SX + 4*SW + SF)      { in = w1; out = w1r; off = SX + 4*SW; }
    else if (i < SX + 4*SW + 2*SF)    { in = w2; out = w2r; off = SX + 4*SW + SF; }
    else return;
    int j = i - off;
    float4 v = in[j];
    v.x = rtf(v.x); v.y = rtf(v.y); v.z = rtf(v.z); v.w = rtf(v.w);
    out[j] = v;
}

// ---------------- generic TF32 tensor-core GEMM (cp.async double buffer) -----
template<int BM, int BN, int WM, int WN, bool TB, bool QKV>
__global__ void __launch_bounds__(256, 2) gemm_tf32(
    const float* __restrict__ A,
    const float* __restrict__ B0, const float* __restrict__ bias0, float* __restrict__ C0,
    const float* __restrict__ B1p, const float* __restrict__ bias1p, float* __restrict__ C1p,
    const float* __restrict__ B2p, const float* __restrict__ bias2p, float* __restrict__ C2p,
    int K, int lda, int ldb, int ldc,
    long long sA1, long long sA2, long long sB1, long long sB2,
    long long sC1, long long sC2, float alpha, int relu, int rnd)
{
    constexpr int MI  = WM / 16;
    constexpr int NJ  = WN / 8;
    constexpr int WGN = BN / WN;
    constexpr int ASTR = 40;
    constexpr int BSTR = TB ? 40 : (BN + 4);
    constexpr int ASZ  = BM * ASTR;
    constexpr int BSZ  = TB ? (BN * 40) : (32 * (BN + 4));
    constexpr int NAV  = BM * 8 / 256;
    constexpr int NBV  = TB ? (BN * 8 / 256) : (8 * BN / 256);

    __shared__ float As[2 * ASZ];
    __shared__ float Bs[2 * BSZ];

    const int tid  = threadIdx.x;
    const int wid  = tid >> 5;
    const int lane = tid & 31;
    const int g    = lane >> 2;
    const int tg   = lane & 3;
    const int wm   = (wid / WGN) * WM;
    const int wn   = (wid % WGN) * WN;

    const float* B    = B0;
    const float* bias = bias0;
    float*       C    = C0;
    long long zb = 0, zh = 0;
    if (QKV) {
        int z = blockIdx.z;
        if (z == 1) { B = B1p; bias = bias1p; C = C1p; }
        else if (z == 2) { B = B2p; bias = bias2p; C = C2p; }
    } else {
        int z = blockIdx.z;
        zb = z / HH; zh = z % HH;
    }

    const float* Ab = A + zb * sA1 + zh * sA2 + (size_t)blockIdx.y * BM * lda;
    const float* Bb = B + zb * sB1 + zh * sB2 +
                      (TB ? (size_t)blockIdx.x * BN * ldb : (size_t)blockIdx.x * BN);
    float* Cb = C + zb * sC1 + zh * sC2 +
                (size_t)blockIdx.y * BM * ldc + (size_t)blockIdx.x * BN;

    const uint32_t sA_base = (uint32_t)__cvta_generic_to_shared(As);
    const uint32_t sB_base = (uint32_t)__cvta_generic_to_shared(Bs);

    auto issue = [&](int k0, int st) {
        uint32_t abuf = sA_base + st * ASZ * 4;
#pragma unroll
        for (int i = 0; i < NAV; i++) {
            int idx = tid + i * 256;
            int m = idx >> 3, cv = idx & 7;
            cp16(abuf + (m * ASTR + cv * 4) * 4,
                 Ab + (size_t)m * lda + k0 + cv * 4);
        }
        uint32_t bbuf = sB_base + st * BSZ * 4;
#pragma unroll
        for (int i = 0; i < NBV; i++) {
            int idx = tid + i * 256;
            if (TB) {
                int n = idx >> 3, cv = idx & 7;
                cp16(bbuf + (n * BSTR + cv * 4) * 4,
                     Bb + (size_t)n * ldb + k0 + cv * 4);
            } else {
                int r = idx / (BN / 4), cv = idx % (BN / 4);
                cp16(bbuf + (r * BSTR + cv * 4) * 4,
                     Bb + (size_t)(k0 + r) * ldb + cv * 4);
            }
        }
        cp_commit();
    };

    float c[MI][NJ][4];
#pragma unroll
    for (int mi = 0; mi < MI; mi++)
#pragma unroll
        for (int j = 0; j < NJ; j++)
#pragma unroll
            for (int r = 0; r < 4; r++) c[mi][j][r] = 0.f;

    const int nK = K / 32;
    issue(0, 0);

    for (int kc = 0; kc < nK; kc++) {
        const int st = kc & 1;
        if (kc + 1 < nK) {
            issue((kc + 1) * 32, st ^ 1);
            cp_wait<1>();
        } else {
            cp_wait<0>();
        }
        __syncthreads();

        const float* Ac = As + st * ASZ;
        const float* Bc = Bs + st * BSZ;
#pragma unroll
        for (int kk = 0; kk < 4; kk++) {
            const int ks = kk * 8;
            uint32_t af[MI][4], bf[NJ][2];
#pragma unroll
            for (int mi = 0; mi < MI; mi++) {
                int m = wm + mi * 16 + g;
                float2 p0 = *(const float2*)&Ac[m * ASTR + ks + 2 * tg];
                float2 p1 = *(const float2*)&Ac[(m + 8) * ASTR + ks + 2 * tg];
                af[mi][0] = __float_as_uint(p0.x);
                af[mi][1] = __float_as_uint(p1.x);
                af[mi][2] = __float_as_uint(p0.y);
                af[mi][3] = __float_as_uint(p1.y);
            }
#pragma unroll
            for (int j = 0; j < NJ; j++) {
                int n = wn + j * 8 + g;
                if (TB) {
                    float2 q = *(const float2*)&Bc[n * BSTR + ks + 2 * tg];
                    bf[j][0] = __float_as_uint(q.x);
                    bf[j][1] = __float_as_uint(q.y);
                } else {
                    bf[j][0] = __float_as_uint(Bc[(ks + 2 * tg)     * BSTR + n]);
                    bf[j][1] = __float_as_uint(Bc[(ks + 2 * tg + 1) * BSTR + n]);
                }
            }
#pragma unroll
            for (int mi = 0; mi < MI; mi++)
#pragma unroll
                for (int j = 0; j < NJ; j++) mma8(c[mi][j], af[mi], bf[j]);
        }
        __syncthreads();
    }

#pragma unroll
    for (int mi = 0; mi < MI; mi++) {
        int r0 = wm + mi * 16 + g;
#pragma unroll
        for (int j = 0; j < NJ; j++) {
            int col = wn + j * 8 + tg * 2;
            float2 bb = make_float2(0.f, 0.f);
            if (bias) bb = *(const float2*)(bias + (size_t)blockIdx.x * BN + col);
            float v0 = c[mi][j][0] * alpha + bb.x;
            float v1 = c[mi][j][1] * alpha + bb.y;
            float v2 = c[mi][j][2] * alpha + bb.x;
            float v3 = c[mi][j][3] * alpha + bb.y;
            if (relu) {
                v0 = fmaxf(v0, 0.f); v1 = fmaxf(v1, 0.f);
                v2 = fmaxf(v2, 0.f); v3 = fmaxf(v3, 0.f);
            }
            if (rnd) { v0 = rtf(v0); v1 = rtf(v1); v2 = rtf(v2); v3 = rtf(v3); }
            *(float2*)(Cb + (size_t)r0 * ldc + col)       = make_float2(v0, v1);
            *(float2*)(Cb + (size_t)(r0 + 8) * ldc + col) = make_float2(v2, v3);
        }
    }
}

// ---------------- stats: Q@K^T tile -> per-block softmax partials ONLY --------
__global__ void __launch_bounds__(256, 2) stats_k64(
    const float* __restrict__ Q, const float* __restrict__ Km,
    float* __restrict__ pm, float* __restrict__ ps)
{
    constexpr int STR = 72;
    __shared__ float As[128 * STR];
    __shared__ float Bs[128 * STR];
    __shared__ float sm_m[128][4];
    __shared__ float sm_s[128][4];

    const int tid  = threadIdx.x;
    const int wid  = tid >> 5;
    const int lane = tid & 31;
    const int g    = lane >> 2;
    const int tg   = lane & 3;
    const int wm   = (wid >> 2) * 64;
    const int wn   = (wid & 3) * 32;

    const int z = blockIdx.z;
    const int b = z / HH, h = z % HH;
    const size_t base = (size_t)b * SS * DD + (size_t)h * DK;
    const int row0 = blockIdx.y * 128;
    const int col0 = blockIdx.x * 128;

    const uint32_t sA = (uint32_t)__cvta_generic_to_shared(As);
    const uint32_t sB = (uint32_t)__cvta_generic_to_shared(Bs);

#pragma unroll
    for (int i = 0; i < 8; i++) {
        int idx = tid + i * 256;
        int m = idx >> 4, cv = idx & 15;
        cp16(sA + (m * STR + cv * 4) * 4, Q  + base + (size_t)(row0 + m) * DD + cv * 4);
        cp16(sB + (m * STR + cv * 4) * 4, Km + base + (size_t)(col0 + m) * DD + cv * 4);
    }
    cp_commit();
    cp_wait<0>();
    __syncthreads();

    float c[4][4][4];
#pragma unroll
    for (int mi = 0; mi < 4; mi++)
#pragma unroll
        for (int j = 0; j < 4; j++)
#pragma unroll
            for (int r = 0; r < 4; r++) c[mi][j][r] = 0.f;

#pragma unroll
    for (int kk = 0; kk < 8; kk++) {
        const int ks = kk * 8;
        uint32_t af[4][4], bf[4][2];
#pragma unroll
        for (int mi = 0; mi < 4; mi++) {
            int m = wm + mi * 16 + g;
            float2 p0 = *(const float2*)&As[m * STR + ks + 2 * tg];
            float2 p1 = *(const float2*)&As[(m + 8) * STR + ks + 2 * tg];
            af[mi][0] = __float_as_uint(p0.x);
            af[mi][1] = __float_as_uint(p1.x);
            af[mi][2] = __float_as_uint(p0.y);
            af[mi][3] = __float_as_uint(p1.y);
        }
#pragma unroll
        for (int j = 0; j < 4; j++) {
            int n = wn + j * 8 + g;
            float2 q = *(const float2*)&Bs[n * STR + ks + 2 * tg];
            bf[j][0] = __float_as_uint(q.x);
            bf[j][1] = __float_as_uint(q.y);
        }
#pragma unroll
        for (int mi = 0; mi < 4; mi++)
#pragma unroll
            for (int j = 0; j < 4; j++) mma8(c[mi][j], af[mi], bf[j]);
    }

    // scale + per-row partial reduction over this 128-col block (no score write)
#pragma unroll
    for (int mi = 0; mi < 4; mi++) {
#pragma unroll
        for (int j = 0; j < 4; j++)
#pragma unroll
            for (int r = 0; r < 4; r++) c[mi][j][r] *= 0.125f;
#pragma unroll
        for (int half = 0; half < 2; half++) {
            float m = -3.0e38f;
#pragma unroll
            for (int j = 0; j < 4; j++)
                m = fmaxf(m, fmaxf(c[mi][j][half*2], c[mi][j][half*2+1]));
            m = fmaxf(m, __shfl_xor_sync(0xffffffffu, m, 1));
            m = fmaxf(m, __shfl_xor_sync(0xffffffffu, m, 2));
            float s = 0.f;
#pragma unroll
            for (int j = 0; j < 4; j++)
                s += __expf(c[mi][j][half*2] - m) + __expf(c[mi][j][half*2+1] - m);
            s += __shfl_xor_sync(0xffffffffu, s, 1);
            s += __shfl_xor_sync(0xffffffffu, s, 2);
            if (tg == 0) {
                int row = wm + mi * 16 + g + half * 8;
                sm_m[row][wid & 3] = m;
                sm_s[row][wid & 3] = s;
            }
        }
    }
    __syncthreads();

    if (tid < 128) {
        float m0 = sm_m[tid][0], m1 = sm_m[tid][1], m2 = sm_m[tid][2], m3 = sm_m[tid][3];
        float m = fmaxf(fmaxf(m0, m1), fmaxf(m2, m3));
        float s = sm_s[tid][0] * __expf(m0 - m) + sm_s[tid][1] * __expf(m1 - m)
                + sm_s[tid][2] * __expf(m2 - m) + sm_s[tid][3] * __expf(m3 - m);
        size_t pidx = ((size_t)z * NBLK + blockIdx.x) * SS + row0 + tid;
        pm[pidx] = m;
        ps[pidx] = s;
    }
}

// ---------------- combine partials -> per-row (max, 1/sum) --------------------
__global__ void rowstats(const float* __restrict__ pm, const float* __restrict__ ps,
                         float* __restrict__ rm, float* __restrict__ ri)
{
    int idx = blockIdx.x * blockDim.x + threadIdx.x;   // z*SS + row
    if (idx >= BB * HH * SS) return;
    int z = idx / SS, row = idx % SS;
    float m = -3.0e38f;
    float mv[NBLK];
#pragma unroll
    for (int blk = 0; blk < NBLK; blk++) {
        mv[blk] = pm[((size_t)z * NBLK + blk) * SS + row];
        m = fmaxf(m, mv[blk]);
    }
    float s = 0.f;
#pragma unroll
    for (int blk = 0; blk < NBLK; blk++)
        s += ps[((size_t)z * NBLK + blk) * SS + row] * __expf(mv[blk] - m);
    rm[idx] = m;
    ri[idx] = 1.0f / s;
}

// ---------------- attn_pv: recompute S, write attn ONCE, ctx = P @ V ----------
// Block: 128 q-rows of one (b,h). Q tile resident; K/V 64-col chunks double-
// buffered via cp.async. S recomputed bitwise-identically to stats_k64.
#define QSTR 72
#define KSTR 72
#define VSTR 68
#define PSTR 72
#define APV_SMEM ((128*QSTR + 128*PSTR + 2*64*KSTR + 2*64*VSTR + 256) * 4)
__global__ void __launch_bounds__(256) attn_pv(
    const float* __restrict__ Q, const float* __restrict__ Km,
    const float* __restrict__ V,
    const float* __restrict__ rm, const float* __restrict__ ri,
    float* __restrict__ attn, float* __restrict__ ctx)
{
    extern __shared__ float sm[];
    float* Qs  = sm;                         // 128 x QSTR
    float* Ps  = Qs + 128 * QSTR;            // 128 x PSTR
    float* Ks  = Ps + 128 * PSTR;            // 2 x 64 x KSTR
    float* Vs  = Ks + 2 * 64 * KSTR;         // 2 x 64 x VSTR
    float* s_m = Vs + 2 * 64 * VSTR;         // 128
    float* s_i = s_m + 128;                  // 128

    const int tid  = threadIdx.x;
    const int wid  = tid >> 5;
    const int lane = tid & 31;
    const int g    = lane >> 2;
    const int tg   = lane & 3;
    const int wm   = (wid >> 1) * 32;   // 4 row tiles of 32
    const int wn   = (wid & 1) * 32;    // 2 col tiles of 32

    const int z = blockIdx.y;
    const int b = z / HH, h = z % HH;
    const size_t base = (size_t)b * SS * DD + (size_t)h * DK;
    const int row0 = blockIdx.x * 128;
    float* Ab = attn + (size_t)z * SS * SS + (size_t)row0 * SS;

    const uint32_t sQ = (uint32_t)__cvta_generic_to_shared(Qs);
    const uint32_t sK = (uint32_t)__cvta_generic_to_shared(Ks);
    const uint32_t sV = (uint32_t)__cvta_generic_to_shared(Vs);

    if (tid < 128) {
        s_m[tid] = rm[(size_t)z * SS + row0 + tid];
        s_i[tid] = ri[(size_t)z * SS + row0 + tid];
    }

    auto issueKV = [&](int cc, int st) {
#pragma unroll
        for (int i = 0; i < 4; i++) {
            int idx = tid + i * 256;
            int r = idx >> 4, cv = idx & 15;
            cp16(sK + (st * 64 * KSTR + r * KSTR + cv * 4) * 4,
                 Km + base + (size_t)(cc * 64 + r) * DD + cv * 4);
            cp16(sV + (st * 64 * VSTR + r * VSTR + cv * 4) * 4,
                 V + base + (size_t)(cc * 64 + r) * DD + cv * 4);
        }
        cp_commit();
    };

    // Q tile + first KV chunk in group 0
#pragma unroll
    for (int i = 0; i < 8; i++) {
        int idx = tid + i * 256;
        int m = idx >> 4, cv = idx & 15;
        cp16(sQ + (m * QSTR + cv * 4) * 4, Q + base + (size_t)(row0 + m) * DD + cv * 4);
    }
    issueKV(0, 0);

    float acc[2][4][4];
#pragma unroll
    for (int mi = 0; mi < 2; mi++)
#pragma unroll
        for (int j = 0; j < 4; j++)
#pragma unroll
            for (int r = 0; r < 4; r++) acc[mi][j][r] = 0.f;

    for (int cc = 0; cc < SS / 64; cc++) {
        const int st = cc & 1;
        if (cc + 1 < SS / 64) {
            issueKV(cc + 1, st ^ 1);
            cp_wait<1>();
        } else {
            cp_wait<0>();
        }
        __syncthreads();   // KV[st] (and Q, stats on cc=0) ready; Ps free

        const float* Kc = Ks + st * 64 * KSTR;
        const float* Vc = Vs + st * 64 * VSTR;

        // ---- S = Q @ Kc^T : 128x64, warp tile 32x32 ----
        float c[2][4][4];
#pragma unroll
        for (int mi = 0; mi < 2; mi++)
#pragma unroll
            for (int j = 0; j < 4; j++)
#pragma unroll
                for (int r = 0; r < 4; r++) c[mi][j][r] = 0.f;

#pragma unroll
        for (int kk = 0; kk < 8; kk++) {
            const int ks = kk * 8;
            uint32_t af[2][4], bf[4][2];
#pragma unroll
            for (int mi = 0; mi < 2; mi++) {
                int m = wm + mi * 16 + g;
                float2 p0 = *(const float2*)&Qs[m * QSTR + ks + 2 * tg];
                float2 p1 = *(const float2*)&Qs[(m + 8) * QSTR + ks + 2 * tg];
                af[mi][0] = __float_as_uint(p0.x);
                af[mi][1] = __float_as_uint(p1.x);
                af[mi][2] = __float_as_uint(p0.y);
                af[mi][3] = __float_as_uint(p1.y);
            }
#pragma unroll
            for (int j = 0; j < 4; j++) {
                int n = wn + j * 8 + g;
                float2 q = *(const float2*)&Kc[n * KSTR + ks + 2 * tg];
                bf[j][0] = __float_as_uint(q.x);
                bf[j][1] = __float_as_uint(q.y);
            }
#pragma unroll
            for (int mi = 0; mi < 2; mi++)
#pragma unroll
                for (int j = 0; j < 4; j++) mma8(c[mi][j], af[mi], bf[j]);
        }

        // ---- normalize + stage P into Ps ----
#pragma unroll
        for (int mi = 0; mi < 2; mi++) {
#pragma unroll
            for (int half = 0; half < 2; half++) {
                int row = wm + mi * 16 + g + half * 8;
                float m = s_m[row], inv = s_i[row];
#pragma unroll
                for (int j = 0; j < 4; j++) {
                    float p0 = rtf(__expf(c[mi][j][half*2]   * 0.125f - m) * inv);
                    float p1 = rtf(__expf(c[mi][j][half*2+1] * 0.125f - m) * inv);
                    *(float2*)&Ps[row * PSTR + wn + j * 8 + 2 * tg] = make_float2(p0, p1);
                }
            }
        }
        __syncthreads();   // Ps complete

        // ---- write attn (coalesced from smem) ----
#pragma unroll
        for (int i = 0; i < 8; i++) {
            int idx = tid + i * 256;
            int row = idx >> 4, cv = idx & 15;
            *(float4*)(Ab + (size_t)row * SS + cc * 64 + cv * 4) =
                *(const float4*)&Ps[row * PSTR + cv * 4];
        }

        // ---- ctx += P @ Vc : 128x64, warp tile 32x32 ----
#pragma unroll
        for (int kk = 0; kk < 8; kk++) {
            const int ks = kk * 8;
            uint32_t af[2][4], bf[4][2];
#pragma unroll
            for (int mi = 0; mi < 2; mi++) {
                int m = wm + mi * 16 + g;
                float2 p0 = *(const float2*)&Ps[m * PSTR + ks + 2 * tg];
                float2 p1 = *(const float2*)&Ps[(m + 8) * PSTR + ks + 2 * tg];
                af[mi][0] = __float_as_uint(p0.x);
                af[mi][1] = __float_as_uint(p1.x);
                af[mi][2] = __float_as_uint(p0.y);
                af[mi][3] = __float_as_uint(p1.y);
            }
#pragma unroll
            for (int j = 0; j < 4; j++) {
                int n = wn + j * 8 + g;
                bf[j][0] = __float_as_uint(Vc[(ks + 2 * tg)     * VSTR + n]);
                bf[j][1] = __float_as_uint(Vc[(ks + 2 * tg + 1) * VSTR + n]);
            }
#pragma unroll
            for (int mi = 0; mi < 2; mi++)
#pragma unroll
                for (int j = 0; j < 4; j++) mma8(acc[mi][j], af[mi], bf[j]);
        }
        // next loop's top __syncthreads protects Ps from early overwrite
    }

    // write ctx (tf32-rounded; feeds Wo GEMM)
#pragma unroll
    for (int mi = 0; mi < 2; mi++) {
        int r0 = row0 + wm + mi * 16 + g;
#pragma unroll
        for (int j = 0; j < 4; j++) {
            int col = wn + j * 8 + tg * 2;
            *(float2*)(ctx + base + (size_t)r0 * DD + col) =
                make_float2(rtf(acc[mi][j][0]), rtf(acc[mi][j][1]));
            *(float2*)(ctx + base + (size_t)(r0 + 8) * DD + col) =
                make_float2(rtf(acc[mi][j][2]), rtf(acc[mi][j][3]));
        }
    }
}

// ---------------- residual + layernorm, one block per row ---------------------
__global__ void add_ln_kernel(const float* __restrict__ x, const float* __restrict__ y,
                              const float* __restrict__ g, const float* __restrict__ be,
                              float* __restrict__ out, int rnd)
{
    size_t row = blockIdx.x;
    const float* px = x + row * DD;
    const float* py = y + row * DD;
    float* po = out + row * DD;
    int t = threadIdx.x;
    __shared__ float red[256];

    float a0 = px[t]       + py[t];
    float a1 = px[t + 256] + py[t + 256];
    float a2 = px[t + 512] + py[t + 512];

    red[t] = a0 + a1 + a2; __syncthreads();
    for (int s = 128; s > 0; s >>= 1) { if (t < s) red[t] += red[t + s]; __syncthreads(); }
    float mean = red[0] * (1.0f / DD); __syncthreads();

    float d0 = a0 - mean, d1 = a1 - mean, d2 = a2 - mean;
    red[t] = d0 * d0 + d1 * d1 + d2 * d2; __syncthreads();
    for (int s = 128; s > 0; s >>= 1) { if (t < s) red[t] += red[t + s]; __syncthreads(); }
    float rstd = rsqrtf(red[0] * (1.0f / DD) + 1e-5f);

    float o0 = d0 * rstd * g[t]       + be[t];
    float o1 = d1 * rstd * g[t + 256] + be[t + 256];
    float o2 = d2 * rstd * g[t + 512] + be[t + 512];
    if (rnd) { o0 = rtf(o0); o1 = rtf(o1); o2 = rtf(o2); }
    po[t] = o0; po[t + 256] = o1; po[t + 512] = o2;
}

// ---------------- launcher ----------------------------------------------------
extern "C" void kernel_launch(void* const* d_in, const int* in_sizes, int n_in,
                              void* d_out, int out_size)
{
    const float* x   = (const float*)d_in[0];
    const float* Wq  = (const float*)d_in[1];
    const float* bq  = (const float*)d_in[2];
    const float* Wk  = (const float*)d_in[3];
    const float* bk  = (const float*)d_in[4];
    const float* Wv  = (const float*)d_in[5];
    const float* bv  = (const float*)d_in[6];
    const float* Wo  = (const float*)d_in[7];
    const float* bo  = (const float*)d_in[8];
    const float* W1  = (const float*)d_in[9];
    const float* b1  = (const float*)d_in[10];
    const float* W2  = (const float*)d_in[11];
    const float* b2  = (const float*)d_in[12];
    const float* g1  = (const float*)d_in[13];
    const float* be1 = (const float*)d_in[14];
    const float* g2  = (const float*)d_in[15];
    const float* be2 = (const float*)d_in[16];

    float* out  = (float*)d_out;                 // x2: [2,2048,768]
    float* attn = out + X2_ELEMS;                // attn_weights: [2,12,2048,2048]

    float *Qp, *Kp, *Vp, *Cp, *X1p, *T2p, *FFp;
    float *xr, *Wqr, *Wkr, *Wvr, *Wor, *W1r, *W2r;
    float *pmp, *psp, *rmp, *rip;
    cudaGetSymbolAddress((void**)&Qp,  g_Q);
    cudaGetSymbolAddress((void**)&Kp,  g_K);
    cudaGetSymbolAddress((void**)&Vp,  g_V);
    cudaGetSymbolAddress((void**)&Cp,  g_ctx);
    cudaGetSymbolAddress((void**)&X1p, g_x1);
    cudaGetSymbolAddress((void**)&T2p, g_t2);
    cudaGetSymbolAddress((void**)&FFp, g_ff);
    cudaGetSymbolAddress((void**)&xr,  g_xr);
    cudaGetSymbolAddress((void**)&Wqr, g_Wqr);
    cudaGetSymbolAddress((void**)&Wkr, g_Wkr);
    cudaGetSymbolAddress((void**)&Wvr, g_Wvr);
    cudaGetSymbolAddress((void**)&Wor, g_Wor);
    cudaGetSymbolAddress((void**)&W1r, g_W1r);
    cudaGetSymbolAddress((void**)&W2r, g_W2r);
    cudaGetSymbolAddress((void**)&pmp, g_pm);
    cudaGetSymbolAddress((void**)&psp, g_ps);
    cudaGetSymbolAddress((void**)&rmp, g_rm);
    cudaGetSymbolAddress((void**)&rip, g_ri);

    static int attr_set = 0;
    if (!attr_set) {
        cudaFuncSetAttribute(attn_pv, cudaFuncAttributeMaxDynamicSharedMemorySize,
                             APV_SMEM);
        attr_set = 1;
    }

    const long long Z0 = 0;

    // pre-round all GEMM inputs to tf32 (RNA), one merged launch
    {
        constexpr int TOT4 = MM*DD/4 + 4*(DD*DD/4) + 2*(DD*DFF/4);
        round_all<<<(TOT4 + 255) / 256, 256>>>(
            (const float4*)x,  (float4*)xr,
            (const float4*)Wq, (float4*)Wqr,
            (const float4*)Wk, (float4*)Wkr,
            (const float4*)Wv, (float4*)Wvr,
            (const float4*)Wo, (float4*)Wor,
            (const float4*)W1, (float4*)W1r,
            (const float4*)W2, (float4*)W2r);
    }

    // merged Q/K/V projections, outputs rounded
    gemm_tf32<128,128,64,32,false,true><<<dim3(DD/128, MM/128, 3), 256>>>(
        xr, Wqr, bq, Qp, Wkr, bk, Kp, Wvr, bv, Vp,
        DD, DD, DD, DD, Z0,Z0,Z0,Z0,Z0,Z0, 1.f, 0, 1);

    // softmax partials from in-register scores (no score materialization)
    stats_k64<<<dim3(SS/128, SS/128, BB*HH), 256>>>(Qp, Kp, pmp, psp);

    // combine partials into per-row stats
    rowstats<<<(BB*HH*SS + 255) / 256, 256>>>(pmp, psp, rmp, rip);

    // recompute S, write final attn once, ctx = P @ V
    attn_pv<<<dim3(SS/128, BB*HH), 256, APV_SMEM>>>(Qp, Kp, Vp, rmp, rip, attn, Cp);

    // attn_out = ctx @ Wo + bo (fp32 out)
    gemm_tf32<128,128,64,32,false,false><<<dim3(DD/128, MM/128, 1), 256>>>(
        Cp, Wor, bo, T2p, nullptr, nullptr, nullptr, nullptr, nullptr, nullptr,
        DD, DD, DD, DD, Z0,Z0,Z0,Z0,Z0,Z0, 1.f, 0, 0);

    // x1 = LN(x + attn_out), rounded (feeds FFN1)
    add_ln_kernel<<<MM, 256>>>(x, T2p, g1, be1, X1p, 1);

    // ff = relu(x1 @ W1 + b1) rounded; ff2 = ff @ W2 + b2 fp32
    gemm_tf32<128,128,64,32,false,false><<<dim3(DFF/128, MM/128, 1), 256>>>(
        X1p, W1r, b1, FFp, nullptr, nullptr, nullptr, nullptr, nullptr, nullptr,
        DD, DD, DFF, DFF, Z0,Z0,Z0,Z0,Z0,Z0, 1.f, 1, 1);
    gemm_tf32<128,128,64,32,false,false><<<dim3(DD/128, MM/128, 1), 256>>>(
        FFp, W2r, b2, T2p, nullptr, nullptr, nullptr, nullptr, nullptr, nullptr,
        DFF, DFF, DD, DD, Z0,Z0,Z0,Z0,Z0,Z0, 1.f, 0, 0);

    // x2 = LN(x1 + ff2) -> output (fp32)
    add_ln_kernel<<<MM, 256>>>(X1p, T2p, g2, be2, out, 0);
}

// round 10
// speedup vs baseline: 1.6888x; 1.5205x over previous
#include <cuda_runtime.h>
#include <cuda_fp16.h>
#include <cstdint>
#include <cstddef>

#define BB 2
#define SS 2048
#define DD 768
#define HH 12
#define DK 64
#define DFF 3072
#define MM (BB*SS)                 // 4096
#define X2_ELEMS ((size_t)MM*DD)   // 3145728
#define NBLK 16                    // SS/128 col blocks per row

// ---------------- scratch (static device globals; no allocation) -------------
__device__ __half g_Qh[(size_t)MM*DD];
__device__ __half g_Kh[(size_t)MM*DD];
__device__ __half g_Vh[(size_t)MM*DD];
__device__ __half g_Vth[(size_t)BB*HH*DK*SS];   // per-head V transposed [dk][seq]
__device__ __half g_ctxh[(size_t)MM*DD];
__device__ float  g_x1[(size_t)MM*DD];
__device__ __half g_x1h[(size_t)MM*DD];
__device__ float  g_t2[(size_t)MM*DD];
__device__ __half g_ffh[(size_t)MM*DFF];
__device__ __half g_xh[(size_t)MM*DD];
// transposed fp16 weights [N][K]
__device__ __half g_Wqh[(size_t)DD*DD];
__device__ __half g_Wkh[(size_t)DD*DD];
__device__ __half g_Wvh[(size_t)DD*DD];
__device__ __half g_Woh[(size_t)DD*DD];
__device__ __half g_W1h[(size_t)DFF*DD];
__device__ __half g_W2h[(size_t)DD*DFF];
// softmax partials / row stats
__device__ float g_pm[(size_t)BB*HH*NBLK*SS];
__device__ float g_ps[(size_t)BB*HH*NBLK*SS];
__device__ float g_rm[(size_t)BB*HH*SS];
__device__ float g_ri[(size_t)BB*HH*SS];

// ---------------- helpers ----------------------------------------------------
__device__ __forceinline__ void mma16(float* c, const uint32_t* a, const uint32_t* b) {
    asm volatile(
        "mma.sync.aligned.m16n8k16.row.col.f32.f16.f16.f32 "
        "{%0,%1,%2,%3},{%4,%5,%6,%7},{%8,%9},{%0,%1,%2,%3};\n"
        : "+f"(c[0]), "+f"(c[1]), "+f"(c[2]), "+f"(c[3])
        : "r"(a[0]), "r"(a[1]), "r"(a[2]), "r"(a[3]), "r"(b[0]), "r"(b[1]));
}

__device__ __forceinline__ void cp16(uint32_t smem_addr, const void* gptr) {
    asm volatile("cp.async.cg.shared.global [%0], [%1], 16;\n"
                 :: "r"(smem_addr), "l"(gptr));
}
__device__ __forceinline__ void cp_commit() {
    asm volatile("cp.async.commit_group;\n" ::: "memory");
}
template<int N>
__device__ __forceinline__ void cp_wait() {
    asm volatile("cp.async.wait_group %0;\n" :: "n"(N) : "memory");
}
__device__ __forceinline__ uint32_t smem_u32(const void* p) {
    uint32_t a;
    asm("{ .reg .u64 t; cvta.to.shared.u64 t, %1; cvt.u32.u64 %0, t; }" : "=r"(a) : "l"(p));
    return a;
}
__device__ __forceinline__ uint32_t h2u(__half2 h) {
    return *reinterpret_cast<uint32_t*>(&h);
}

// ---------------- prep: x -> fp16 ---------------------------------------------
__global__ void round_x_h(const float4* __restrict__ in, __half2* __restrict__ out, int n4)
{
    int i = blockIdx.x * blockDim.x + threadIdx.x;
    if (i < n4) {
        float4 v = in[i];
        out[i * 2]     = __floats2half2_rn(v.x, v.y);
        out[i * 2 + 1] = __floats2half2_rn(v.z, v.w);
    }
}

// ---------------- prep: weight [R,C] fp32 -> [C,R] fp16 ------------------------
__global__ void tr_round_h(const float* __restrict__ in, __half* __restrict__ out,
                           int R, int C)
{
    __shared__ float t[32][33];
    int c0 = blockIdx.x * 32, r0 = blockIdx.y * 32;
    int x = threadIdx.x, y = threadIdx.y;   // 32 x 8
#pragma unroll
    for (int i = 0; i < 32; i += 8)
        t[y + i][x] = in[(size_t)(r0 + y + i) * C + c0 + x];
    __syncthreads();
#pragma unroll
    for (int i = 0; i < 32; i += 8)
        out[(size_t)(c0 + y + i) * R + r0 + x] = __float2half_rn(t[x][y + i]);
}

// ---------------- prep: per-head V [seq][dk] -> [dk][seq] fp16 -----------------
__global__ void v_transpose(const __half* __restrict__ Vh, __half* __restrict__ Vt)
{
    __shared__ __half t[64][72];
    int z = blockIdx.y;
    int b = z / HH, h = z % HH;
    int s0 = blockIdx.x * 64;
    const __half* src = Vh + (size_t)b * SS * DD + (size_t)h * DK;
    __half* dst = Vt + (size_t)z * DK * SS;
    int x = threadIdx.x, y = threadIdx.y;    // 64 x 4
#pragma unroll
    for (int i = 0; i < 64; i += 4)
        t[y + i][x] = src[(size_t)(s0 + y + i) * DD + x];
    __syncthreads();
#pragma unroll
    for (int i = 0; i < 64; i += 4)
        dst[(size_t)(y + i) * SS + s0 + x] = t[x][y + i];
}

// ---------------- fp16 dense GEMM:  C = A[M,K] @ Bt[N,K]^T + bias --------------
// 128x128 tile, BK=32, 8 warps (warp 64x32), m16n8k16. z selects (Bt,bias,out).
#define DSTR 20   // u32 units per 32-half row (40 halves incl pad)
__global__ void __launch_bounds__(256, 2) dense_h(
    const __half* __restrict__ A,
    const __half* __restrict__ Bt0, const float* __restrict__ bias0,
    __half* __restrict__ H0, float* __restrict__ F0,
    const __half* __restrict__ Bt1, const float* __restrict__ bias1,
    __half* __restrict__ H1, float* __restrict__ F1,
    const __half* __restrict__ Bt2, const float* __restrict__ bias2,
    __half* __restrict__ H2, float* __restrict__ F2,
    int K, int Ntot, int relu)
{
    __shared__ uint32_t As[2 * 128 * DSTR];
    __shared__ uint32_t Bs[2 * 128 * DSTR];

    const int tid  = threadIdx.x;
    const int wid  = tid >> 5;
    const int lane = tid & 31;
    const int g    = lane >> 2;
    const int tg   = lane & 3;
    const int wm   = (wid >> 2) * 64;
    const int wn   = (wid & 3) * 32;

    const __half* Bt = Bt0; const float* bias = bias0;
    __half* H = H0; float* F = F0;
    if (blockIdx.z == 1) { Bt = Bt1; bias = bias1; H = H1; F = F1; }
    else if (blockIdx.z == 2) { Bt = Bt2; bias = bias2; H = H2; F = F2; }

    const int m0 = blockIdx.y * 128;
    const int n0 = blockIdx.x * 128;
    const __half* Ab = A + (size_t)m0 * K;
    const __half* Bb = Bt + (size_t)n0 * K;

    const uint32_t sA = smem_u32(As);
    const uint32_t sB = smem_u32(Bs);

    auto issue = [&](int ch, int st) {
        int k0 = ch * 32;
        uint32_t abuf = sA + st * (128 * DSTR) * 4;
        uint32_t bbuf = sB + st * (128 * DSTR) * 4;
#pragma unroll
        for (int i = 0; i < 2; i++) {
            int idx = tid + i * 256;
            int r = idx >> 2, c = idx & 3;
            cp16(abuf + (r * DSTR + c * 4) * 4, Ab + (size_t)r * K + k0 + c * 8);
            cp16(bbuf + (r * DSTR + c * 4) * 4, Bb + (size_t)r * K + k0 + c * 8);
        }
        cp_commit();
    };

    float c[4][4][4];
#pragma unroll
    for (int mi = 0; mi < 4; mi++)
#pragma unroll
        for (int j = 0; j < 4; j++)
#pragma unroll
            for (int r = 0; r < 4; r++) c[mi][j][r] = 0.f;

    const int nc = K / 32;
    issue(0, 0);

    for (int kc = 0; kc < nc; kc++) {
        const int st = kc & 1;
        if (kc + 1 < nc) { issue(kc + 1, st ^ 1); cp_wait<1>(); }
        else             { cp_wait<0>(); }
        __syncthreads();

        const uint32_t* Ac = As + st * (128 * DSTR);
        const uint32_t* Bc = Bs + st * (128 * DSTR);
#pragma unroll
        for (int step = 0; step < 2; step++) {
            const int ko = step * 8;
            uint32_t af[4][4], bf[4][2];
#pragma unroll
            for (int mi = 0; mi < 4; mi++) {
                int m = wm + mi * 16 + g;
                af[mi][0] = Ac[m * DSTR + ko + tg];
                af[mi][2] = Ac[m * DSTR + ko + tg + 4];
                af[mi][1] = Ac[(m + 8) * DSTR + ko + tg];
                af[mi][3] = Ac[(m + 8) * DSTR + ko + tg + 4];
            }
#pragma unroll
            for (int j = 0; j < 4; j++) {
                int n = wn + j * 8 + g;
                bf[j][0] = Bc[n * DSTR + ko + tg];
                bf[j][1] = Bc[n * DSTR + ko + tg + 4];
            }
#pragma unroll
            for (int mi = 0; mi < 4; mi++)
#pragma unroll
                for (int j = 0; j < 4; j++) mma16(c[mi][j], af[mi], bf[j]);
        }
        __syncthreads();
    }

    // epilogue
#pragma unroll
    for (int mi = 0; mi < 4; mi++) {
        int r0 = m0 + wm + mi * 16 + g;
#pragma unroll
        for (int j = 0; j < 4; j++) {
            int col = n0 + wn + j * 8 + tg * 2;
            float2 bb = *(const float2*)(bias + col);
            float v0 = c[mi][j][0] + bb.x;
            float v1 = c[mi][j][1] + bb.y;
            float v2 = c[mi][j][2] + bb.x;
            float v3 = c[mi][j][3] + bb.y;
            if (relu) {
                v0 = fmaxf(v0, 0.f); v1 = fmaxf(v1, 0.f);
                v2 = fmaxf(v2, 0.f); v3 = fmaxf(v3, 0.f);
            }
            if (H) {
                *(uint32_t*)(H + (size_t)r0 * Ntot + col)       = h2u(__floats2half2_rn(v0, v1));
                *(uint32_t*)(H + (size_t)(r0 + 8) * Ntot + col) = h2u(__floats2half2_rn(v2, v3));
            }
            if (F) {
                *(float2*)(F + (size_t)r0 * Ntot + col)       = make_float2(v0, v1);
                *(float2*)(F + (size_t)(r0 + 8) * Ntot + col) = make_float2(v2, v3);
            }
        }
    }
}

// ---------------- stats: Q@K^T (fp16) -> per-block softmax partials ------------
#define HSTR 36   // u32 units per 64-half row (72 halves incl pad)
__global__ void __launch_bounds__(256, 2) stats_h(
    const __half* __restrict__ Q, const __half* __restrict__ Km,
    float* __restrict__ pm, float* __restrict__ ps)
{
    __shared__ uint32_t Qs[128 * HSTR];
    __shared__ uint32_t Ks[128 * HSTR];
    __shared__ float sm_m[128][4];
    __shared__ float sm_s[128][4];

    const int tid  = threadIdx.x;
    const int wid  = tid >> 5;
    const int lane = tid & 31;
    const int g    = lane >> 2;
    const int tg   = lane & 3;
    const int wm   = (wid >> 2) * 64;
    const int wn   = (wid & 3) * 32;

    const int z = blockIdx.z;
    const int b = z / HH, h = z % HH;
    const size_t base = (size_t)b * SS * DD + (size_t)h * DK;
    const int row0 = blockIdx.y * 128;
    const int col0 = blockIdx.x * 128;

    const uint32_t sQ = smem_u32(Qs);
    const uint32_t sK = smem_u32(Ks);

#pragma unroll
    for (int i = 0; i < 4; i++) {
        int idx = tid + i * 256;
        int r = idx >> 3, cch = idx & 7;
        cp16(sQ + (r * HSTR + cch * 4) * 4, Q  + base + (size_t)(row0 + r) * DD + cch * 8);
        cp16(sK + (r * HSTR + cch * 4) * 4, Km + base + (size_t)(col0 + r) * DD + cch * 8);
    }
    cp_commit();
    cp_wait<0>();
    __syncthreads();

    float c[4][4][4];
#pragma unroll
    for (int mi = 0; mi < 4; mi++)
#pragma unroll
        for (int j = 0; j < 4; j++)
#pragma unroll
            for (int r = 0; r < 4; r++) c[mi][j][r] = 0.f;

#pragma unroll
    for (int step = 0; step < 4; step++) {
        const int ko = step * 8;
        uint32_t af[4][4], bf[4][2];
#pragma unroll
        for (int mi = 0; mi < 4; mi++) {
            int m = wm + mi * 16 + g;
            af[mi][0] = Qs[m * HSTR + ko + tg];
            af[mi][2] = Qs[m * HSTR + ko + tg + 4];
            af[mi][1] = Qs[(m + 8) * HSTR + ko + tg];
            af[mi][3] = Qs[(m + 8) * HSTR + ko + tg + 4];
        }
#pragma unroll
        for (int j = 0; j < 4; j++) {
            int n = wn + j * 8 + g;
            bf[j][0] = Ks[n * HSTR + ko + tg];
            bf[j][1] = Ks[n * HSTR + ko + tg + 4];
        }
#pragma unroll
        for (int mi = 0; mi < 4; mi++)
#pragma unroll
            for (int j = 0; j < 4; j++) mma16(c[mi][j], af[mi], bf[j]);
    }

#pragma unroll
    for (int mi = 0; mi < 4; mi++) {
#pragma unroll
        for (int j = 0; j < 4; j++)
#pragma unroll
            for (int r = 0; r < 4; r++) c[mi][j][r] *= 0.125f;
#pragma unroll
        for (int half = 0; half < 2; half++) {
            float m = -3.0e38f;
#pragma unroll
            for (int j = 0; j < 4; j++)
                m = fmaxf(m, fmaxf(c[mi][j][half*2], c[mi][j][half*2+1]));
            m = fmaxf(m, __shfl_xor_sync(0xffffffffu, m, 1));
            m = fmaxf(m, __shfl_xor_sync(0xffffffffu, m, 2));
            float s = 0.f;
#pragma unroll
            for (int j = 0; j < 4; j++)
                s += __expf(c[mi][j][half*2] - m) + __expf(c[mi][j][half*2+1] - m);
            s += __shfl_xor_sync(0xffffffffu, s, 1);
            s += __shfl_xor_sync(0xffffffffu, s, 2);
            if (tg == 0) {
                int row = wm + mi * 16 + g + half * 8;
                sm_m[row][wid & 3] = m;
                sm_s[row][wid & 3] = s;
            }
        }
    }
    __syncthreads();

    if (tid < 128) {
        float m0 = sm_m[tid][0], m1 = sm_m[tid][1], m2 = sm_m[tid][2], m3 = sm_m[tid][3];
        float m = fmaxf(fmaxf(m0, m1), fmaxf(m2, m3));
        float s = sm_s[tid][0] * __expf(m0 - m) + sm_s[tid][1] * __expf(m1 - m)
                + sm_s[tid][2] * __expf(m2 - m) + sm_s[tid][3] * __expf(m3 - m);
        size_t pidx = ((size_t)z * NBLK + blockIdx.x) * SS + row0 + tid;
        pm[pidx] = m;
        ps[pidx] = s;
    }
}

// ---------------- combine partials -> per-row (max, 1/sum) --------------------
__global__ void rowstats(const float* __restrict__ pm, const float* __restrict__ ps,
                         float* __restrict__ rm, float* __restrict__ ri)
{
    int idx = blockIdx.x * blockDim.x + threadIdx.x;
    if (idx >= BB * HH * SS) return;
    int z = idx / SS, row = idx % SS;
    float m = -3.0e38f;
    float mv[NBLK];
#pragma unroll
    for (int blk = 0; blk < NBLK; blk++) {
        mv[blk] = pm[((size_t)z * NBLK + blk) * SS + row];
        m = fmaxf(m, mv[blk]);
    }
    float s = 0.f;
#pragma unroll
    for (int blk = 0; blk < NBLK; blk++)
        s += ps[((size_t)z * NBLK + blk) * SS + row] * __expf(mv[blk] - m);
    rm[idx] = m;
    ri[idx] = 1.0f / s;
}

// ---------------- attn_pv: recompute S (fp16), write attn fp32, ctx = P@V -----
// Block: 128 q-rows of one (b,h). Q resident; K (seq x dk) & Vt (dk x seq)
// chunks double-buffered. S chain bitwise-identical to stats_h.
#define APV_SMEM ((128*HSTR + 128*HSTR + 2*64*HSTR + 2*64*HSTR) * 4 + 1024)
__global__ void __launch_bounds__(256) attn_pv_h(
    const __half* __restrict__ Q, const __half* __restrict__ Km,
    const __half* __restrict__ Vt,
    const float* __restrict__ rm, const float* __restrict__ ri,
    float* __restrict__ attn, __half* __restrict__ ctx)
{
    extern __shared__ uint32_t smu[];
    uint32_t* Qs = smu;                       // 128 x HSTR
    uint32_t* Ps = Qs + 128 * HSTR;           // 128 x HSTR
    uint32_t* Ks = Ps + 128 * HSTR;           // 2 x 64 x HSTR
    uint32_t* Vs = Ks + 2 * 64 * HSTR;        // 2 x 64 x HSTR
    float* s_m = (float*)(Vs + 2 * 64 * HSTR);
    float* s_i = s_m + 128;

    const int tid  = threadIdx.x;
    const int wid  = tid >> 5;
    const int lane = tid & 31;
    const int g    = lane >> 2;
    const int tg   = lane & 3;
    const int wm   = (wid >> 1) * 32;   // 4 row groups of 32
    const int wn   = (wid & 1) * 32;    // 2 col groups of 32

    const int z = blockIdx.y;
    const int b = z / HH, h = z % HH;
    const size_t base = (size_t)b * SS * DD + (size_t)h * DK;
    const int row0 = blockIdx.x * 128;
    float* Ab = attn + (size_t)z * SS * SS + (size_t)row0 * SS;
    const __half* Vz = Vt + (size_t)z * DK * SS;

    const uint32_t sQ = smem_u32(Qs);
    const uint32_t sK = smem_u32(Ks);
    const uint32_t sV = smem_u32(Vs);

    if (tid < 128) {
        s_m[tid] = rm[(size_t)z * SS + row0 + tid];
        s_i[tid] = ri[(size_t)z * SS + row0 + tid];
    }

    auto issueKV = [&](int cc, int st) {
#pragma unroll
        for (int i = 0; i < 2; i++) {
            int idx = tid + i * 256;
            int r = idx >> 3, cch = idx & 7;
            cp16(sK + ((st * 64 + r) * HSTR + cch * 4) * 4,
                 Km + base + (size_t)(cc * 64 + r) * DD + cch * 8);
            cp16(sV + ((st * 64 + r) * HSTR + cch * 4) * 4,
                 Vz + (size_t)r * SS + cc * 64 + cch * 8);
        }
        cp_commit();
    };

#pragma unroll
    for (int i = 0; i < 4; i++) {
        int idx = tid + i * 256;
        int r = idx >> 3, cch = idx & 7;
        cp16(sQ + (r * HSTR + cch * 4) * 4, Q + base + (size_t)(row0 + r) * DD + cch * 8);
    }
    issueKV(0, 0);

    float acc[2][4][4];
#pragma unroll
    for (int mi = 0; mi < 2; mi++)
#pragma unroll
        for (int j = 0; j < 4; j++)
#pragma unroll
            for (int r = 0; r < 4; r++) acc[mi][j][r] = 0.f;

    for (int cc = 0; cc < SS / 64; cc++) {
        const int st = cc & 1;
        if (cc + 1 < SS / 64) { issueKV(cc + 1, st ^ 1); cp_wait<1>(); }
        else                  { cp_wait<0>(); }
        __syncthreads();   // KV[st] ready; Ps from prev iter consumed

        const uint32_t* Kc = Ks + st * 64 * HSTR;
        const uint32_t* Vc = Vs + st * 64 * HSTR;

        // ---- S = Q @ Kc^T (k = dk = 64) ----
        float c[2][4][4];
#pragma unroll
        for (int mi = 0; mi < 2; mi++)
#pragma unroll
            for (int j = 0; j < 4; j++)
#pragma unroll
                for (int r = 0; r < 4; r++) c[mi][j][r] = 0.f;

#pragma unroll
        for (int step = 0; step < 4; step++) {
            const int ko = step * 8;
            uint32_t af[2][4], bf[4][2];
#pragma unroll
            for (int mi = 0; mi < 2; mi++) {
                int m = wm + mi * 16 + g;
                af[mi][0] = Qs[m * HSTR + ko + tg];
                af[mi][2] = Qs[m * HSTR + ko + tg + 4];
                af[mi][1] = Qs[(m + 8) * HSTR + ko + tg];
                af[mi][3] = Qs[(m + 8) * HSTR + ko + tg + 4];
            }
#pragma unroll
            for (int j = 0; j < 4; j++) {
                int n = wn + j * 8 + g;
                bf[j][0] = Kc[n * HSTR + ko + tg];
                bf[j][1] = Kc[n * HSTR + ko + tg + 4];
            }
#pragma unroll
            for (int mi = 0; mi < 2; mi++)
#pragma unroll
                for (int j = 0; j < 4; j++) mma16(c[mi][j], af[mi], bf[j]);
        }

        // ---- normalize: write attn fp32 straight from registers, stage P fp16 ----
#pragma unroll
        for (int mi = 0; mi < 2; mi++) {
#pragma unroll
            for (int half = 0; half < 2; half++) {
                int row = wm + mi * 16 + g + half * 8;
                float m = s_m[row], inv = s_i[row];
#pragma unroll
                for (int j = 0; j < 4; j++) {
                    float p0 = __expf(c[mi][j][half*2]   * 0.125f - m) * inv;
                    float p1 = __expf(c[mi][j][half*2+1] * 0.125f - m) * inv;
                    int col = wn + j * 8 + 2 * tg;
                    *(float2*)(Ab + (size_t)row * SS + cc * 64 + col) = make_float2(p0, p1);
                    Ps[row * HSTR + (wn + j * 8) / 2 + tg] = h2u(__floats2half2_rn(p0, p1));
                }
            }
        }
        __syncthreads();   // Ps complete (cross-warp: PV reads full 64-col rows)

        // ---- ctx += P @ Vc^T (k = seq 64; Vc is [dk][seq]) ----
#pragma unroll
        for (int step = 0; step < 4; step++) {
            const int ko = step * 8;
            uint32_t af[2][4], bf[4][2];
#pragma unroll
            for (int mi = 0; mi < 2; mi++) {
                int m = wm + mi * 16 + g;
                af[mi][0] = Ps[m * HSTR + ko + tg];
                af[mi][2] = Ps[m * HSTR + ko + tg + 4];
                af[mi][1] = Ps[(m + 8) * HSTR + ko + tg];
                af[mi][3] = Ps[(m + 8) * HSTR + ko + tg + 4];
            }
#pragma unroll
            for (int j = 0; j < 4; j++) {
                int n = wn + j * 8 + g;
                bf[j][0] = Vc[n * HSTR + ko + tg];
                bf[j][1] = Vc[n * HSTR + ko + tg + 4];
            }
#pragma unroll
            for (int mi = 0; mi < 2; mi++)
#pragma unroll
                for (int j = 0; j < 4; j++) mma16(acc[mi][j], af[mi], bf[j]);
        }
    }

    // ctx fp16 (feeds Wo GEMM)
#pragma unroll
    for (int mi = 0; mi < 2; mi++) {
        int r0 = row0 + wm + mi * 16 + g;
#pragma unroll
        for (int j = 0; j < 4; j++) {
            int col = wn + j * 8 + tg * 2;
            *(uint32_t*)(ctx + base + (size_t)r0 * DD + col) =
                h2u(__floats2half2_rn(acc[mi][j][0], acc[mi][j][1]));
            *(uint32_t*)(ctx + base + (size_t)(r0 + 8) * DD + col) =
                h2u(__floats2half2_rn(acc[mi][j][2], acc[mi][j][3]));
        }
    }
}

// ---------------- residual + layernorm ----------------------------------------
__global__ void add_ln_kernel(const float* __restrict__ x, const float* __restrict__ y,
                              const float* __restrict__ g, const float* __restrict__ be,
                              float* __restrict__ po, __half* __restrict__ poh)
{
    size_t row = blockIdx.x;
    const float* px = x + row * DD;
    const float* py = y + row * DD;
    int t = threadIdx.x;
    __shared__ float red[256];

    float a0 = px[t]       + py[t];
    float a1 = px[t + 256] + py[t + 256];
    float a2 = px[t + 512] + py[t + 512];

    red[t] = a0 + a1 + a2; __syncthreads();
    for (int s = 128; s > 0; s >>= 1) { if (t < s) red[t] += red[t + s]; __syncthreads(); }
    float mean = red[0] * (1.0f / DD); __syncthreads();

    float d0 = a0 - mean, d1 = a1 - mean, d2 = a2 - mean;
    red[t] = d0 * d0 + d1 * d1 + d2 * d2; __syncthreads();
    for (int s = 128; s > 0; s >>= 1) { if (t < s) red[t] += red[t + s]; __syncthreads(); }
    float rstd = rsqrtf(red[0] * (1.0f / DD) + 1e-5f);

    float o0 = d0 * rstd * g[t]       + be[t];
    float o1 = d1 * rstd * g[t + 256] + be[t + 256];
    float o2 = d2 * rstd * g[t + 512] + be[t + 512];
    po[row * DD + t] = o0; po[row * DD + t + 256] = o1; po[row * DD + t + 512] = o2;
    if (poh) {
        poh[row * DD + t]       = __float2half_rn(o0);
        poh[row * DD + t + 256] = __float2half_rn(o1);
        poh[row * DD + t + 512] = __float2half_rn(o2);
    }
}

// ---------------- launcher ----------------------------------------------------
extern "C" void kernel_launch(void* const* d_in, const int* in_sizes, int n_in,
                              void* d_out, int out_size)
{
    const float* x   = (const float*)d_in[0];
    const float* Wq  = (const float*)d_in[1];
    const float* bq  = (const float*)d_in[2];
    const float* Wk  = (const float*)d_in[3];
    const float* bk  = (const float*)d_in[4];
    const float* Wv  = (const float*)d_in[5];
    const float* bv  = (const float*)d_in[6];
    const float* Wo  = (const float*)d_in[7];
    const float* bo  = (const float*)d_in[8];
    const float* W1  = (const float*)d_in[9];
    const float* b1  = (const float*)d_in[10];
    const float* W2  = (const float*)d_in[11];
    const float* b2  = (const float*)d_in[12];
    const float* g1  = (const float*)d_in[13];
    const float* be1 = (const float*)d_in[14];
    const float* g2  = (const float*)d_in[15];
    const float* be2 = (const float*)d_in[16];

    float* out  = (float*)d_out;                 // x2: [2,2048,768]
    float* attn = out + X2_ELEMS;                // attn_weights: [2,12,2048,2048]

    __half *Qh, *Kh, *Vh, *Vth, *ctxh, *x1h, *ffh, *xh;
    __half *Wqh, *Wkh, *Wvh, *Woh, *W1h, *W2h;
    float *X1p, *T2p, *pmp, *psp, *rmp, *rip;
    cudaGetSymbolAddress((void**)&Qh,   g_Qh);
    cudaGetSymbolAddress((void**)&Kh,   g_Kh);
    cudaGetSymbolAddress((void**)&Vh,   g_Vh);
    cudaGetSymbolAddress((void**)&Vth,  g_Vth);
    cudaGetSymbolAddress((void**)&ctxh, g_ctxh);
    cudaGetSymbolAddress((void**)&x1h,  g_x1h);
    cudaGetSymbolAddress((void**)&ffh,  g_ffh);
    cudaGetSymbolAddress((void**)&xh,   g_xh);
    cudaGetSymbolAddress((void**)&Wqh,  g_Wqh);
    cudaGetSymbolAddress((void**)&Wkh,  g_Wkh);
    cudaGetSymbolAddress((void**)&Wvh,  g_Wvh);
    cudaGetSymbolAddress((void**)&Woh,  g_Woh);
    cudaGetSymbolAddress((void**)&W1h,  g_W1h);
    cudaGetSymbolAddress((void**)&W2h,  g_W2h);
    cudaGetSymbolAddress((void**)&X1p,  g_x1);
    cudaGetSymbolAddress((void**)&T2p,  g_t2);
    cudaGetSymbolAddress((void**)&pmp,  g_pm);
    cudaGetSymbolAddress((void**)&psp,  g_ps);
    cudaGetSymbolAddress((void**)&rmp,  g_rm);
    cudaGetSymbolAddress((void**)&rip,  g_ri);

    static int attr_set = 0;
    if (!attr_set) {
        cudaFuncSetAttribute(attn_pv_h, cudaFuncAttributeMaxDynamicSharedMemorySize,
                             APV_SMEM);
        attr_set = 1;
    }

    // prep: x -> fp16; weights -> transposed fp16 [N][K]
    round_x_h<<<(MM*DD/4 + 255) / 256, 256>>>((const float4*)x, (__half2*)xh, MM*DD/4);
    dim3 trb(32, 8);
    tr_round_h<<<dim3(DD/32, DD/32),  trb>>>(Wq, Wqh, DD, DD);
    tr_round_h<<<dim3(DD/32, DD/32),  trb>>>(Wk, Wkh, DD, DD);
    tr_round_h<<<dim3(DD/32, DD/32),  trb>>>(Wv, Wvh, DD, DD);
    tr_round_h<<<dim3(DD/32, DD/32),  trb>>>(Wo, Woh, DD, DD);
    tr_round_h<<<dim3(DFF/32, DD/32), trb>>>(W1, W1h, DD, DFF);
    tr_round_h<<<dim3(DD/32, DFF/32), trb>>>(W2, W2h, DFF, DD);

    // merged Q/K/V projections (fp16 out)
    dense_h<<<dim3(DD/128, MM/128, 3), 256>>>(
        xh, Wqh, bq, Qh, nullptr, Wkh, bk, Kh, nullptr, Wvh, bv, Vh, nullptr,
        DD, DD, 0);

    // per-head V transpose [seq][dk] -> [dk][seq]
    v_transpose<<<dim3(SS/64, BB*HH), dim3(64, 4)>>>(Vh, Vth);

    // softmax stats from in-register fp16 scores
    stats_h<<<dim3(SS/128, SS/128, BB*HH), 256>>>(Qh, Kh, pmp, psp);
    rowstats<<<(BB*HH*SS + 255) / 256, 256>>>(pmp, psp, rmp, rip);

    // recompute S, write attn (fp32) once, ctx = P @ V (fp16)
    attn_pv_h<<<dim3(SS/128, BB*HH), 256, APV_SMEM>>>(Qh, Kh, Vth, rmp, rip, attn, ctxh);

    // attn_out = ctx @ Wo + bo (fp32 out)
    dense_h<<<dim3(DD/128, MM/128, 1), 256>>>(
        ctxh, Woh, bo, nullptr, T2p, nullptr, nullptr, nullptr, nullptr,
        nullptr, nullptr, nullptr, nullptr, DD, DD, 0);

    // x1 = LN(x + attn_out) -> fp32 + fp16
    add_ln_kernel<<<MM, 256>>>(x, T2p, g1, be1, X1p, x1h);

    // ff = relu(x1 @ W1 + b1) fp16; ff2 = ff @ W2 + b2 fp32
    dense_h<<<dim3(DFF/128, MM/128, 1), 256>>>(
        x1h, W1h, b1, ffh, nullptr, nullptr, nullptr, nullptr, nullptr,
        nullptr, nullptr, nullptr, nullptr, DD, DFF, 1);
    dense_h<<<dim3(DD/128, MM/128, 1), 256>>>(
        ffh, W2h, b2, nullptr, T2p, nullptr, nullptr, nullptr, nullptr,
        nullptr, nullptr, nullptr, nullptr, DFF, DD, 0);

    // x2 = LN(x1 + ff2) -> output
    add_ln_kernel<<<MM, 256>>>(X1p, T2p, g2, be2, out, nullptr);
}

// round 11
// speedup vs baseline: 1.8060x; 1.0694x over previous
#include <cuda_runtime.h>
#include <cuda_fp16.h>
#include <cstdint>
#include <cstddef>

#define BB 2
#define SS 2048
#define DD 768
#define HH 12
#define DK 64
#define DFF 3072
#define MM (BB*SS)                 // 4096
#define X2_ELEMS ((size_t)MM*DD)   // 3145728
#define NBLK 16                    // SS/128 col blocks per row

// ---------------- scratch (static device globals; no allocation) -------------
__device__ __half g_Qh[(size_t)MM*DD];
__device__ __half g_Kh[(size_t)MM*DD];
__device__ __half g_Vh[(size_t)MM*DD];
__device__ __half g_Vth[(size_t)BB*HH*DK*SS];   // per-head V transposed [dk][seq]
__device__ __half g_ctxh[(size_t)MM*DD];
__device__ float  g_x1[(size_t)MM*DD];
__device__ __half g_x1h[(size_t)MM*DD];
__device__ float  g_t2[(size_t)MM*DD];
__device__ __half g_ffh[(size_t)MM*DFF];
__device__ __half g_xh[(size_t)MM*DD];
// transposed fp16 weights [N][K]
__device__ __half g_Wqh[(size_t)DD*DD];
__device__ __half g_Wkh[(size_t)DD*DD];
__device__ __half g_Wvh[(size_t)DD*DD];
__device__ __half g_Woh[(size_t)DD*DD];
__device__ __half g_W1h[(size_t)DFF*DD];
__device__ __half g_W2h[(size_t)DD*DFF];
// softmax partials / row stats
__device__ float g_pm[(size_t)BB*HH*NBLK*SS];
__device__ float g_ps[(size_t)BB*HH*NBLK*SS];
__device__ float g_rm[(size_t)BB*HH*SS];
__device__ float g_ri[(size_t)BB*HH*SS];

// ---------------- helpers ----------------------------------------------------
__device__ __forceinline__ void mma16(float* c, const uint32_t* a, const uint32_t* b) {
    asm volatile(
        "mma.sync.aligned.m16n8k16.row.col.f32.f16.f16.f32 "
        "{%0,%1,%2,%3},{%4,%5,%6,%7},{%8,%9},{%0,%1,%2,%3};\n"
        : "+f"(c[0]), "+f"(c[1]), "+f"(c[2]), "+f"(c[3])
        : "r"(a[0]), "r"(a[1]), "r"(a[2]), "r"(a[3]), "r"(b[0]), "r"(b[1]));
}

__device__ __forceinline__ void cp16(uint32_t smem_addr, const void* gptr) {
    asm volatile("cp.async.cg.shared.global [%0], [%1], 16;\n"
                 :: "r"(smem_addr), "l"(gptr));
}
__device__ __forceinline__ void cp_commit() {
    asm volatile("cp.async.commit_group;\n" ::: "memory");
}
template<int N>
__device__ __forceinline__ void cp_wait() {
    asm volatile("cp.async.wait_group %0;\n" :: "n"(N) : "memory");
}
__device__ __forceinline__ uint32_t smem_u32(const void* p) {
    uint32_t a;
    asm("{ .reg .u64 t; cvta.to.shared.u64 t, %1; cvt.u32.u64 %0, t; }" : "=r"(a) : "l"(p));
    return a;
}
__device__ __forceinline__ uint32_t h2u(__half2 h) {
    return *reinterpret_cast<uint32_t*>(&h);
}
// logical u32 k-index -> physical (k-permute: (tg,tg+4) <-> (2tg,2tg+1))
__device__ __forceinline__ int kperm(int l) {
    int r = l & 7;
    int p = (r < 4) ? (2 * r) : (2 * (r - 4) + 1);
    return (l & ~7) | p;
}

// ---------------- merged prep: x->fp16 + 6 weight transposes -------------------
// blocks [0,3072): x convert. blocks [3072,9984): 32x32 transpose tiles.
#define PREP_XBLK 3072
__global__ void prep_all(
    const float4* __restrict__ x,  __half2* __restrict__ xh,
    const float* __restrict__ wq, __half* __restrict__ wqh,
    const float* __restrict__ wk, __half* __restrict__ wkh,
    const float* __restrict__ wv, __half* __restrict__ wvh,
    const float* __restrict__ wo, __half* __restrict__ woh,
    const float* __restrict__ w1, __half* __restrict__ w1h,
    const float* __restrict__ w2, __half* __restrict__ w2h)
{
    int bid = blockIdx.x;
    int tid = threadIdx.x;
    if (bid < PREP_XBLK) {
        int i = bid * 256 + tid;
        float4 v = x[i];
        xh[i * 2]     = __floats2half2_rn(v.x, v.y);
        xh[i * 2 + 1] = __floats2half2_rn(v.z, v.w);
        return;
    }
    int t = bid - PREP_XBLK;
    const float* in; __half* out; int R, C;
    if      (t < 576)  { in = wq; out = wqh; R = DD;  C = DD;  }
    else if (t < 1152) { in = wk; out = wkh; R = DD;  C = DD;  t -= 576; }
    else if (t < 1728) { in = wv; out = wvh; R = DD;  C = DD;  t -= 1152; }
    else if (t < 2304) { in = wo; out = woh; R = DD;  C = DD;  t -= 1728; }
    else if (t < 4608) { in = w1; out = w1h; R = DD;  C = DFF; t -= 2304; }
    else               { in = w2; out = w2h; R = DFF; C = DD;  t -= 4608; }
    int nx = C / 32;
    int c0 = (t % nx) * 32, r0 = (t / nx) * 32;
    __shared__ float tt[32][33];
    int xx = tid & 31, yy = tid >> 5;    // 32 x 8
#pragma unroll
    for (int i = 0; i < 32; i += 8)
        tt[yy + i][xx] = in[(size_t)(r0 + yy + i) * C + c0 + xx];
    __syncthreads();
#pragma unroll
    for (int i = 0; i < 32; i += 8)
        out[(size_t)(c0 + yy + i) * R + r0 + xx] = __float2half_rn(tt[xx][yy + i]);
}

// ---------------- prep: per-head V [seq][dk] -> [dk][seq] fp16 -----------------
__global__ void v_transpose(const __half* __restrict__ Vh, __half* __restrict__ Vt)
{
    __shared__ __half t[64][72];
    int z = blockIdx.y;
    int b = z / HH, h = z % HH;
    int s0 = blockIdx.x * 64;
    const __half* src = Vh + (size_t)b * SS * DD + (size_t)h * DK;
    __half* dst = Vt + (size_t)z * DK * SS;
    int x = threadIdx.x, y = threadIdx.y;    // 64 x 4
#pragma unroll
    for (int i = 0; i < 64; i += 4)
        t[y + i][x] = src[(size_t)(s0 + y + i) * DD + x];
    __syncthreads();
#pragma unroll
    for (int i = 0; i < 64; i += 4)
        dst[(size_t)(y + i) * SS + s0 + x] = t[x][y + i];
}

// ---------------- fp16 dense GEMM:  C = A[M,K] @ Bt[N,K]^T + bias --------------
// 128x128 tile, BK=32, 8 warps (warp 64x32), m16n8k16, k-permuted LDS.64.
#define DSTR 24   // u32 units per 32-half row; banks 24g+2tg conflict-free
__global__ void __launch_bounds__(256, 2) dense_h(
    const __half* __restrict__ A,
    const __half* __restrict__ Bt0, const float* __restrict__ bias0,
    __half* __restrict__ H0, float* __restrict__ F0,
    const __half* __restrict__ Bt1, const float* __restrict__ bias1,
    __half* __restrict__ H1, float* __restrict__ F1,
    const __half* __restrict__ Bt2, const float* __restrict__ bias2,
    __half* __restrict__ H2, float* __restrict__ F2,
    int K, int Ntot, int relu)
{
    __shared__ uint32_t As[2 * 128 * DSTR];
    __shared__ uint32_t Bs[2 * 128 * DSTR];

    const int tid  = threadIdx.x;
    const int wid  = tid >> 5;
    const int lane = tid & 31;
    const int g    = lane >> 2;
    const int tg   = lane & 3;
    const int wm   = (wid >> 2) * 64;
    const int wn   = (wid & 3) * 32;

    const __half* Bt = Bt0; const float* bias = bias0;
    __half* H = H0; float* F = F0;
    if (blockIdx.z == 1) { Bt = Bt1; bias = bias1; H = H1; F = F1; }
    else if (blockIdx.z == 2) { Bt = Bt2; bias = bias2; H = H2; F = F2; }

    const int m0 = blockIdx.y * 128;
    const int n0 = blockIdx.x * 128;
    const __half* Ab = A + (size_t)m0 * K;
    const __half* Bb = Bt + (size_t)n0 * K;

    const uint32_t sA = smem_u32(As);
    const uint32_t sB = smem_u32(Bs);

    auto issue = [&](int ch, int st) {
        int k0 = ch * 32;
        uint32_t abuf = sA + st * (128 * DSTR) * 4;
        uint32_t bbuf = sB + st * (128 * DSTR) * 4;
#pragma unroll
        for (int i = 0; i < 2; i++) {
            int idx = tid + i * 256;
            int r = idx >> 2, c = idx & 3;
            cp16(abuf + (r * DSTR + c * 4) * 4, Ab + (size_t)r * K + k0 + c * 8);
            cp16(bbuf + (r * DSTR + c * 4) * 4, Bb + (size_t)r * K + k0 + c * 8);
        }
        cp_commit();
    };

    float c[4][4][4];
#pragma unroll
    for (int mi = 0; mi < 4; mi++)
#pragma unroll
        for (int j = 0; j < 4; j++)
#pragma unroll
            for (int r = 0; r < 4; r++) c[mi][j][r] = 0.f;

    const int nc = K / 32;
    issue(0, 0);

    for (int kc = 0; kc < nc; kc++) {
        const int st = kc & 1;
        if (kc + 1 < nc) { issue(kc + 1, st ^ 1); cp_wait<1>(); }
        else             { cp_wait<0>(); }
        __syncthreads();

        const uint32_t* Ac = As + st * (128 * DSTR);
        const uint32_t* Bc = Bs + st * (128 * DSTR);
#pragma unroll
        for (int step = 0; step < 2; step++) {
            const int ko = step * 8;
            uint32_t af[4][4], bf[4][2];
#pragma unroll
            for (int mi = 0; mi < 4; mi++) {
                int m = wm + mi * 16 + g;
                uint2 p0 = *(const uint2*)&Ac[m * DSTR + ko + 2 * tg];
                uint2 p1 = *(const uint2*)&Ac[(m + 8) * DSTR + ko + 2 * tg];
                af[mi][0] = p0.x; af[mi][2] = p0.y;
                af[mi][1] = p1.x; af[mi][3] = p1.y;
            }
#pragma unroll
            for (int j = 0; j < 4; j++) {
                int n = wn + j * 8 + g;
                uint2 q = *(const uint2*)&Bc[n * DSTR + ko + 2 * tg];
                bf[j][0] = q.x; bf[j][1] = q.y;
            }
#pragma unroll
            for (int mi = 0; mi < 4; mi++)
#pragma unroll
                for (int j = 0; j < 4; j++) mma16(c[mi][j], af[mi], bf[j]);
        }
        __syncthreads();
    }

    // epilogue
#pragma unroll
    for (int mi = 0; mi < 4; mi++) {
        int r0 = m0 + wm + mi * 16 + g;
#pragma unroll
        for (int j = 0; j < 4; j++) {
            int col = n0 + wn + j * 8 + tg * 2;
            float2 bb = *(const float2*)(bias + col);
            float v0 = c[mi][j][0] + bb.x;
            float v1 = c[mi][j][1] + bb.y;
            float v2 = c[mi][j][2] + bb.x;
            float v3 = c[mi][j][3] + bb.y;
            if (relu) {
                v0 = fmaxf(v0, 0.f); v1 = fmaxf(v1, 0.f);
                v2 = fmaxf(v2, 0.f); v3 = fmaxf(v3, 0.f);
            }
            if (H) {
                *(uint32_t*)(H + (size_t)r0 * Ntot + col)       = h2u(__floats2half2_rn(v0, v1));
                *(uint32_t*)(H + (size_t)(r0 + 8) * Ntot + col) = h2u(__floats2half2_rn(v2, v3));
            }
            if (F) {
                *(float2*)(F + (size_t)r0 * Ntot + col)       = make_float2(v0, v1);
                *(float2*)(F + (size_t)(r0 + 8) * Ntot + col) = make_float2(v2, v3);
            }
        }
    }
}

// ---------------- stats: Q@K^T (fp16) -> per-block softmax partials ------------
#define HSTR 40   // u32 units per 64-half row; banks 8g+2tg conflict-free
__global__ void __launch_bounds__(256, 2) stats_h(
    const __half* __restrict__ Q, const __half* __restrict__ Km,
    float* __restrict__ pm, float* __restrict__ ps)
{
    __shared__ uint32_t Qs[128 * HSTR];
    __shared__ uint32_t Ks[128 * HSTR];
    __shared__ float sm_m[128][4];
    __shared__ float sm_s[128][4];

    const int tid  = threadIdx.x;
    const int wid  = tid >> 5;
    const int lane = tid & 31;
    const int g    = lane >> 2;
    const int tg   = lane & 3;
    const int wm   = (wid >> 2) * 64;
    const int wn   = (wid & 3) * 32;

    const int z = blockIdx.z;
    const int b = z / HH, h = z % HH;
    const size_t base = (size_t)b * SS * DD + (size_t)h * DK;
    const int row0 = blockIdx.y * 128;
    const int col0 = blockIdx.x * 128;

    const uint32_t sQ = smem_u32(Qs);
    const uint32_t sK = smem_u32(Ks);

#pragma unroll
    for (int i = 0; i < 4; i++) {
        int idx = tid + i * 256;
        int r = idx >> 3, cch = idx & 7;
        cp16(sQ + (r * HSTR + cch * 4) * 4, Q  + base + (size_t)(row0 + r) * DD + cch * 8);
        cp16(sK + (r * HSTR + cch * 4) * 4, Km + base + (size_t)(col0 + r) * DD + cch * 8);
    }
    cp_commit();
    cp_wait<0>();
    __syncthreads();

    float c[4][4][4];
#pragma unroll
    for (int mi = 0; mi < 4; mi++)
#pragma unroll
        for (int j = 0; j < 4; j++)
#pragma unroll
            for (int r = 0; r < 4; r++) c[mi][j][r] = 0.f;

#pragma unroll
    for (int step = 0; step < 4; step++) {
        const int ko = step * 8;
        uint32_t af[4][4], bf[4][2];
#pragma unroll
        for (int mi = 0; mi < 4; mi++) {
            int m = wm + mi * 16 + g;
            uint2 p0 = *(const uint2*)&Qs[m * HSTR + ko + 2 * tg];
            uint2 p1 = *(const uint2*)&Qs[(m + 8) * HSTR + ko + 2 * tg];
            af[mi][0] = p0.x; af[mi][2] = p0.y;
            af[mi][1] = p1.x; af[mi][3] = p1.y;
        }
#pragma unroll
        for (int j = 0; j < 4; j++) {
            int n = wn + j * 8 + g;
            uint2 q = *(const uint2*)&Ks[n * HSTR + ko + 2 * tg];
            bf[j][0] = q.x; bf[j][1] = q.y;
        }
#pragma unroll
        for (int mi = 0; mi < 4; mi++)
#pragma unroll
            for (int j = 0; j < 4; j++) mma16(c[mi][j], af[mi], bf[j]);
    }

#pragma unroll
    for (int mi = 0; mi < 4; mi++) {
#pragma unroll
        for (int j = 0; j < 4; j++)
#pragma unroll
            for (int r = 0; r < 4; r++) c[mi][j][r] *= 0.125f;
#pragma unroll
        for (int half = 0; half < 2; half++) {
            float m = -3.0e38f;
#pragma unroll
            for (int j = 0; j < 4; j++)
                m = fmaxf(m, fmaxf(c[mi][j][half*2], c[mi][j][half*2+1]));
            m = fmaxf(m, __shfl_xor_sync(0xffffffffu, m, 1));
            m = fmaxf(m, __shfl_xor_sync(0xffffffffu, m, 2));
            float s = 0.f;
#pragma unroll
            for (int j = 0; j < 4; j++)
                s += __expf(c[mi][j][half*2] - m) + __expf(c[mi][j][half*2+1] - m);
            s += __shfl_xor_sync(0xffffffffu, s, 1);
            s += __shfl_xor_sync(0xffffffffu, s, 2);
            if (tg == 0) {
                int row = wm + mi * 16 + g + half * 8;
                sm_m[row][wid & 3] = m;
                sm_s[row][wid & 3] = s;
            }
        }
    }
    __syncthreads();

    if (tid < 128) {
        float m0 = sm_m[tid][0], m1 = sm_m[tid][1], m2 = sm_m[tid][2], m3 = sm_m[tid][3];
        float m = fmaxf(fmaxf(m0, m1), fmaxf(m2, m3));
        float s = sm_s[tid][0] * __expf(m0 - m) + sm_s[tid][1] * __expf(m1 - m)
                + sm_s[tid][2] * __expf(m2 - m) + sm_s[tid][3] * __expf(m3 - m);
        size_t pidx = ((size_t)z * NBLK + blockIdx.x) * SS + row0 + tid;
        pm[pidx] = m;
        ps[pidx] = s;
    }
}

// ---------------- combine partials -> per-row (max, 1/sum) --------------------
__global__ void rowstats(const float* __restrict__ pm, const float* __restrict__ ps,
                         float* __restrict__ rm, float* __restrict__ ri)
{
    int idx = blockIdx.x * blockDim.x + threadIdx.x;
    if (idx >= BB * HH * SS) return;
    int z = idx / SS, row = idx % SS;
    float m = -3.0e38f;
    float mv[NBLK];
#pragma unroll
    for (int blk = 0; blk < NBLK; blk++) {
        mv[blk] = pm[((size_t)z * NBLK + blk) * SS + row];
        m = fmaxf(m, mv[blk]);
    }
    float s = 0.f;
#pragma unroll
    for (int blk = 0; blk < NBLK; blk++)
        s += ps[((size_t)z * NBLK + blk) * SS + row] * __expf(mv[blk] - m);
    rm[idx] = m;
    ri[idx] = 1.0f / s;
}

// ---------------- attn_pv: recompute S (fp16), write attn fp32, ctx = P@V -----
#define APV_SMEM ((128*HSTR * 4) * 4 + 1024)
__global__ void __launch_bounds__(256) attn_pv_h(
    const __half* __restrict__ Q, const __half* __restrict__ Km,
    const __half* __restrict__ Vt,
    const float* __restrict__ rm, const float* __restrict__ ri,
    float* __restrict__ attn, __half* __restrict__ ctx)
{
    extern __shared__ uint32_t smu[];
    uint32_t* Qs = smu;                       // 128 x HSTR
    uint32_t* Ps = Qs + 128 * HSTR;           // 128 x HSTR (k-permuted layout)
    uint32_t* Ks = Ps + 128 * HSTR;           // 2 x 64 x HSTR
    uint32_t* Vs = Ks + 2 * 64 * HSTR;        // 2 x 64 x HSTR
    float* s_m = (float*)(Vs + 2 * 64 * HSTR);
    float* s_i = s_m + 128;

    const int tid  = threadIdx.x;
    const int wid  = tid >> 5;
    const int lane = tid & 31;
    const int g    = lane >> 2;
    const int tg   = lane & 3;
    const int wm   = (wid >> 1) * 32;   // 4 row groups of 32
    const int wn   = (wid & 1) * 32;    // 2 col groups of 32

    const int z = blockIdx.y;
    const int b = z / HH, h = z % HH;
    const size_t base = (size_t)b * SS * DD + (size_t)h * DK;
    const int row0 = blockIdx.x * 128;
    float* Ab = attn + (size_t)z * SS * SS + (size_t)row0 * SS;
    const __half* Vz = Vt + (size_t)z * DK * SS;

    const uint32_t sQ = smem_u32(Qs);
    const uint32_t sK = smem_u32(Ks);
    const uint32_t sV = smem_u32(Vs);

    if (tid < 128) {
        s_m[tid] = rm[(size_t)z * SS + row0 + tid];
        s_i[tid] = ri[(size_t)z * SS + row0 + tid];
    }

    auto issueKV = [&](int cc, int st) {
#pragma unroll
        for (int i = 0; i < 2; i++) {
            int idx = tid + i * 256;
            int r = idx >> 3, cch = idx & 7;
            cp16(sK + ((st * 64 + r) * HSTR + cch * 4) * 4,
                 Km + base + (size_t)(cc * 64 + r) * DD + cch * 8);
            cp16(sV + ((st * 64 + r) * HSTR + cch * 4) * 4,
                 Vz + (size_t)r * SS + cc * 64 + cch * 8);
        }
        cp_commit();
    };

#pragma unroll
    for (int i = 0; i < 4; i++) {
        int idx = tid + i * 256;
        int r = idx >> 3, cch = idx & 7;
        cp16(sQ + (r * HSTR + cch * 4) * 4, Q + base + (size_t)(row0 + r) * DD + cch * 8);
    }
    issueKV(0, 0);

    float acc[2][4][4];
#pragma unroll
    for (int mi = 0; mi < 2; mi++)
#pragma unroll
        for (int j = 0; j < 4; j++)
#pragma unroll
            for (int r = 0; r < 4; r++) acc[mi][j][r] = 0.f;

    for (int cc = 0; cc < SS / 64; cc++) {
        const int st = cc & 1;
        if (cc + 1 < SS / 64) { issueKV(cc + 1, st ^ 1); cp_wait<1>(); }
        else                  { cp_wait<0>(); }
        __syncthreads();   // KV[st] ready; Ps from prev iter consumed

        const uint32_t* Kc = Ks + st * 64 * HSTR;
        const uint32_t* Vc = Vs + st * 64 * HSTR;

        // ---- S = Q @ Kc^T (k = dk = 64); permuted LDS.64, matches stats_h ----
        float c[2][4][4];
#pragma unroll
        for (int mi = 0; mi < 2; mi++)
#pragma unroll
            for (int j = 0; j < 4; j++)
#pragma unroll
                for (int r = 0; r < 4; r++) c[mi][j][r] = 0.f;

#pragma unroll
        for (int step = 0; step < 4; step++) {
            const int ko = step * 8;
            uint32_t af[2][4], bf[4][2];
#pragma unroll
            for (int mi = 0; mi < 2; mi++) {
                int m = wm + mi * 16 + g;
                uint2 p0 = *(const uint2*)&Qs[m * HSTR + ko + 2 * tg];
                uint2 p1 = *(const uint2*)&Qs[(m + 8) * HSTR + ko + 2 * tg];
                af[mi][0] = p0.x; af[mi][2] = p0.y;
                af[mi][1] = p1.x; af[mi][3] = p1.y;
            }
#pragma unroll
            for (int j = 0; j < 4; j++) {
                int n = wn + j * 8 + g;
                uint2 q = *(const uint2*)&Kc[n * HSTR + ko + 2 * tg];
                bf[j][0] = q.x; bf[j][1] = q.y;
            }
#pragma unroll
            for (int mi = 0; mi < 2; mi++)
#pragma unroll
                for (int j = 0; j < 4; j++) mma16(c[mi][j], af[mi], bf[j]);
        }

        // ---- normalize: write attn fp32 from registers, stage P (k-permuted) ----
#pragma unroll
        for (int mi = 0; mi < 2; mi++) {
#pragma unroll
            for (int half = 0; half < 2; half++) {
                int row = wm + mi * 16 + g + half * 8;
                float m = s_m[row], inv = s_i[row];
#pragma unroll
                for (int j = 0; j < 4; j++) {
                    float p0 = __expf(c[mi][j][half*2]   * 0.125f - m) * inv;
                    float p1 = __expf(c[mi][j][half*2+1] * 0.125f - m) * inv;
                    int col = wn + j * 8 + 2 * tg;
                    *(float2*)(Ab + (size_t)row * SS + cc * 64 + col) = make_float2(p0, p1);
                    Ps[row * HSTR + kperm(wn / 2 + 4 * j + tg)] = h2u(__floats2half2_rn(p0, p1));
                }
            }
        }
        __syncthreads();   // Ps complete

        // ---- ctx += P @ Vc^T: af permuted LDS.64 (pre-permuted Ps), bf straight ----
#pragma unroll
        for (int step = 0; step < 4; step++) {
            const int ko = step * 8;
            uint32_t af[2][4], bf[4][2];
#pragma unroll
            for (int mi = 0; mi < 2; mi++) {
                int m = wm + mi * 16 + g;
                uint2 p0 = *(const uint2*)&Ps[m * HSTR + ko + 2 * tg];
                uint2 p1 = *(const uint2*)&Ps[(m + 8) * HSTR + ko + 2 * tg];
                af[mi][0] = p0.x; af[mi][2] = p0.y;
                af[mi][1] = p1.x; af[mi][3] = p1.y;
            }
#pragma unroll
            for (int j = 0; j < 4; j++) {
                int n = wn + j * 8 + g;
                bf[j][0] = Vc[n * HSTR + ko + tg];
                bf[j][1] = Vc[n * HSTR + ko + tg + 4];
            }
#pragma unroll
            for (int mi = 0; mi < 2; mi++)
#pragma unroll
                for (int j = 0; j < 4; j++) mma16(acc[mi][j], af[mi], bf[j]);
        }
    }

    // ctx fp16 (feeds Wo GEMM)
#pragma unroll
    for (int mi = 0; mi < 2; mi++) {
        int r0 = row0 + wm + mi * 16 + g;
#pragma unroll
        for (int j = 0; j < 4; j++) {
            int col = wn + j * 8 + tg * 2;
            *(uint32_t*)(ctx + base + (size_t)r0 * DD + col) =
                h2u(__floats2half2_rn(acc[mi][j][0], acc[mi][j][1]));
            *(uint32_t*)(ctx + base + (size_t)(r0 + 8) * DD + col) =
                h2u(__floats2half2_rn(acc[mi][j][2], acc[mi][j][3]));
        }
    }
}

// ---------------- residual + layernorm ----------------------------------------
__global__ void add_ln_kernel(const float* __restrict__ x, const float* __restrict__ y,
                              const float* __restrict__ g, const float* __restrict__ be,
                              float* __restrict__ po, __half* __restrict__ poh)
{
    size_t row = blockIdx.x;
    const float* px = x + row * DD;
    const float* py = y + row * DD;
    int t = threadIdx.x;
    __shared__ float red[256];

    float a0 = px[t]       + py[t];
    float a1 = px[t + 256] + py[t + 256];
    float a2 = px[t + 512] + py[t + 512];

    red[t] = a0 + a1 + a2; __syncthreads();
    for (int s = 128; s > 0; s >>= 1) { if (t < s) red[t] += red[t + s]; __syncthreads(); }
    float mean = red[0] * (1.0f / DD); __syncthreads();

    float d0 = a0 - mean, d1 = a1 - mean, d2 = a2 - mean;
    red[t] = d0 * d0 + d1 * d1 + d2 * d2; __syncthreads();
    for (int s = 128; s > 0; s >>= 1) { if (t < s) red[t] += red[t + s]; __syncthreads(); }
    float rstd = rsqrtf(red[0] * (1.0f / DD) + 1e-5f);

    float o0 = d0 * rstd * g[t]       + be[t];
    float o1 = d1 * rstd * g[t + 256] + be[t + 256];
    float o2 = d2 * rstd * g[t + 512] + be[t + 512];
    po[row * DD + t] = o0; po[row * DD + t + 256] = o1; po[row * DD + t + 512] = o2;
    if (poh) {
        poh[row * DD + t]       = __float2half_rn(o0);
        poh[row * DD + t + 256] = __float2half_rn(o1);
        poh[row * DD + t + 512] = __float2half_rn(o2);
    }
}

// ---------------- launcher ----------------------------------------------------
extern "C" void kernel_launch(void* const* d_in, const int* in_sizes, int n_in,
                              void* d_out, int out_size)
{
    const float* x   = (const float*)d_in[0];
    const float* Wq  = (const float*)d_in[1];
    const float* bq  = (const float*)d_in[2];
    const float* Wk  = (const float*)d_in[3];
    const float* bk  = (const float*)d_in[4];
    const float* Wv  = (const float*)d_in[5];
    const float* bv  = (const float*)d_in[6];
    const float* Wo  = (const float*)d_in[7];
    const float* bo  = (const float*)d_in[8];
    const float* W1  = (const float*)d_in[9];
    const float* b1  = (const float*)d_in[10];
    const float* W2  = (const float*)d_in[11];
    const float* b2  = (const float*)d_in[12];
    const float* g1  = (const float*)d_in[13];
    const float* be1 = (const float*)d_in[14];
    const float* g2  = (const float*)d_in[15];
    const float* be2 = (const float*)d_in[16];

    float* out  = (float*)d_out;                 // x2: [2,2048,768]
    float* attn = out + X2_ELEMS;                // attn_weights: [2,12,2048,2048]

    __half *Qh, *Kh, *Vh, *Vth, *ctxh, *x1h, *ffh, *xh;
    __half *Wqh, *Wkh, *Wvh, *Woh, *W1h, *W2h;
    float *X1p, *T2p, *pmp, *psp, *rmp, *rip;
    cudaGetSymbolAddress((void**)&Qh,   g_Qh);
    cudaGetSymbolAddress((void**)&Kh,   g_Kh);
    cudaGetSymbolAddress((void**)&Vh,   g_Vh);
    cudaGetSymbolAddress((void**)&Vth,  g_Vth);
    cudaGetSymbolAddress((void**)&ctxh, g_ctxh);
    cudaGetSymbolAddress((void**)&x1h,  g_x1h);
    cudaGetSymbolAddress((void**)&ffh,  g_ffh);
    cudaGetSymbolAddress((void**)&xh,   g_xh);
    cudaGetSymbolAddress((void**)&Wqh,  g_Wqh);
    cudaGetSymbolAddress((void**)&Wkh,  g_Wkh);
    cudaGetSymbolAddress((void**)&Wvh,  g_Wvh);
    cudaGetSymbolAddress((void**)&Woh,  g_Woh);
    cudaGetSymbolAddress((void**)&W1h,  g_W1h);
    cudaGetSymbolAddress((void**)&W2h,  g_W2h);
    cudaGetSymbolAddress((void**)&X1p,  g_x1);
    cudaGetSymbolAddress((void**)&T2p,  g_t2);
    cudaGetSymbolAddress((void**)&pmp,  g_pm);
    cudaGetSymbolAddress((void**)&psp,  g_ps);
    cudaGetSymbolAddress((void**)&rmp,  g_rm);
    cudaGetSymbolAddress((void**)&rip,  g_ri);

    static int attr_set = 0;
    if (!attr_set) {
        cudaFuncSetAttribute(attn_pv_h, cudaFuncAttributeMaxDynamicSharedMemorySize,
                             APV_SMEM);
        attr_set = 1;
    }

    // merged prep: x -> fp16 + all weight transposes (one launch)
    prep_all<<<PREP_XBLK + 6912, 256>>>(
        (const float4*)x, (__half2*)xh,
        Wq, Wqh, Wk, Wkh, Wv, Wvh, Wo, Woh, W1, W1h, W2, W2h);

    // merged Q/K/V projections (fp16 out)
    dense_h<<<dim3(DD/128, MM/128, 3), 256>>>(
        xh, Wqh, bq, Qh, nullptr, Wkh, bk, Kh, nullptr, Wvh, bv, Vh, nullptr,
        DD, DD, 0);

    // per-head V transpose [seq][dk] -> [dk][seq]
    v_transpose<<<dim3(SS/64, BB*HH), dim3(64, 4)>>>(Vh, Vth);

    // softmax stats from in-register fp16 scores
    stats_h<<<dim3(SS/128, SS/128, BB*HH), 256>>>(Qh, Kh, pmp, psp);
    rowstats<<<(BB*HH*SS + 255) / 256, 256>>>(pmp, psp, rmp, rip);

    // recompute S, write attn (fp32) once, ctx = P @ V (fp16)
    attn_pv_h<<<dim3(SS/128, BB*HH), 256, APV_SMEM>>>(Qh, Kh, Vth, rmp, rip, attn, ctxh);

    // attn_out = ctx @ Wo + bo (fp32 out)
    dense_h<<<dim3(DD/128, MM/128, 1), 256>>>(
        ctxh, Woh, bo, nullptr, T2p, nullptr, nullptr, nullptr, nullptr,
        nullptr, nullptr, nullptr, nullptr, DD, DD, 0);

    // x1 = LN(x + attn_out) -> fp32 + fp16
    add_ln_kernel<<<MM, 256>>>(x, T2p, g1, be1, X1p, x1h);

    // ff = relu(x1 @ W1 + b1) fp16; ff2 = ff @ W2 + b2 fp32
    dense_h<<<dim3(DFF/128, MM/128, 1), 256>>>(
        x1h, W1h, b1, ffh, nullptr, nullptr, nullptr, nullptr, nullptr,
        nullptr, nullptr, nullptr, nullptr, DD, DFF, 1);
    dense_h<<<dim3(DD/128, MM/128, 1), 256>>>(
        ffh, W2h, b2, nullptr, T2p, nullptr, nullptr, nullptr, nullptr,
        nullptr, nullptr, nullptr, nullptr, DFF, DD, 0);

    // x2 = LN(x1 + ff2) -> output
    add_ln_kernel<<<MM, 256>>>(X1p, T2p, g2, be2, out, nullptr);
}